// round 13
// baseline (speedup 1.0000x reference)
#include <cuda_runtime.h>
#include <cuda_bf16.h>
#include <math.h>
#include <stdint.h>

#define B_ 32
#define SH_ 256
#define WH_ 512
#define DH_ 1024
#define NSEQ_ 512
#define NR_ 8192
#define NCH_W0 9
#define NCH_W1 16
#define NCH_Q 16
#define NCH_DEC 25
#define TILE_BYTES 16384
#define PAIR_BYTES 32768
#define TG_SMEM 135168
#define DEC_SMEM (131072 + 32768)
#define WR_SMEM (131072 + 2 * 49152)
#define SR_SMEM (65536 + 16384 + 16384)

#define DEVBUF __device__ __align__(16)
DEVBUF float g_pre_s[NSEQ_ * 2048];
DEVBUF float g_sent_enc[NSEQ_ * 512];
DEVBUF float g_pre_w[NR_ * 4096];
DEVBUF float g_q[NR_ * 512];
DEVBUF float g_pre_d[NR_ * 4096];
DEVBUF float g_dec_out[NR_ * 1024];
DEVBUF float g_sWh0P[2 * SH_ * SH_ * 4];
DEVBUF float g_sWh1P[2 * SH_ * SH_ * 4];
DEVBUF float g_clsWT[15 * 1024];
DEVBUF float g_shs[2 * 2 * 32 * 256];
DEVBUF unsigned char g_stageA[64ul * 16 * PAIR_BYTES];
DEVBUF unsigned char g_stageD[64ul * 25 * PAIR_BYTES];
DEVBUF unsigned char g_stageS[4ul * 5 * PAIR_BYTES];
DEVBUF unsigned char g_stageS2[4ul * 8 * PAIR_BYTES];
DEVBUF unsigned char g_stB_s0[16ul * 5 * PAIR_BYTES];
DEVBUF unsigned char g_stB_s1[16ul * 8 * PAIR_BYTES];
DEVBUF unsigned char g_stB_w0[32ul * NCH_W0 * PAIR_BYTES];
DEVBUF unsigned char g_stB_w1[32ul * NCH_W1 * PAIR_BYTES];
DEVBUF unsigned char g_stB_q[4ul * NCH_Q * PAIR_BYTES];
DEVBUF unsigned char g_stB_dec[32ul * NCH_DEC * PAIR_BYTES];
DEVBUF unsigned char g_stDWr[32ul * 16 * PAIR_BYTES];
DEVBUF unsigned char g_stWw[4ul * 16 * 8 * PAIR_BYTES];
DEVBUF unsigned char g_hstage[128ul * PAIR_BYTES];
DEVBUF __nv_bfloat16 g_hsplitH[2][B_ * DH_];
DEVBUF __nv_bfloat16 g_hsplitL[2][B_ * DH_];
DEVBUF unsigned g_barT[8 * 32];
DEVBUF unsigned g_barT2[8 * 32];
DEVBUF unsigned g_barT3[8 * 32];

__device__ __forceinline__ float sigm(float x) { return 1.f / (1.f + expf(-x)); }
__device__ __forceinline__ unsigned swz(unsigned o) { return o ^ ((o >> 3) & 0x70); }

__device__ __forceinline__ uint32_t smem_u32(const void* p) {
    uint32_t a;
    asm("{ .reg .u64 t; cvta.to.shared.u64 t, %1; cvt.u32.u64 %0, t; }" : "=r"(a) : "l"(p));
    return a;
}
__device__ __forceinline__ void cp_async16(uint32_t dst, const void* src) {
    asm volatile("cp.async.cg.shared.global [%0], [%1], 16;" :: "r"(dst), "l"(src) : "memory");
}
__device__ __forceinline__ void cp_commit() {
    asm volatile("cp.async.commit_group;" ::: "memory");
}
template <int N>
__device__ __forceinline__ void cp_wait() {
    asm volatile("cp.async.wait_group %0;" :: "n"(N) : "memory");
}
__device__ __forceinline__ void cp_bulk(uint32_t dst, const void* src, uint32_t bytes,
                                        uint32_t mbar) {
    asm volatile(
        "cp.async.bulk.shared::cta.global.mbarrier::complete_tx::bytes [%0], [%1], %2, [%3];"
        :: "r"(dst), "l"(src), "r"(bytes), "r"(mbar) : "memory");
}
__device__ __forceinline__ void mbar_init(uint32_t a, uint32_t c) {
    asm volatile("mbarrier.init.shared.b64 [%0], %1;" :: "r"(a), "r"(c) : "memory");
}
__device__ __forceinline__ void mbar_expect_tx(uint32_t a, uint32_t bytes) {
    asm volatile("mbarrier.arrive.expect_tx.shared.b64 _, [%0], %1;"
                 :: "r"(a), "r"(bytes) : "memory");
}
__device__ __forceinline__ void mbar_wait(uint32_t a, uint32_t par) {
    asm volatile(
        "{\n\t.reg .pred P1;\n\tLW%=:\n\t"
        "mbarrier.try_wait.parity.acquire.cta.shared::cta.b64 P1, [%0], %1, 0x989680;\n\t"
        "@P1 bra.uni LD%=;\n\tbra.uni LW%=;\n\tLD%=:\n\t}"
        :: "r"(a), "r"(par) : "memory");
}
__device__ __forceinline__ void fence_async() {
    asm volatile("fence.proxy.async.shared::cta;" ::: "memory");
}
__device__ __forceinline__ void ldm_x4(uint32_t* r, uint32_t addr) {
    asm volatile("ldmatrix.sync.aligned.m8n8.x4.shared.b16 {%0,%1,%2,%3}, [%4];"
                 : "=r"(r[0]), "=r"(r[1]), "=r"(r[2]), "=r"(r[3]) : "r"(addr));
}
__device__ __forceinline__ void mma16816(float* d, const uint32_t* a, const uint32_t* b) {
    asm volatile(
        "mma.sync.aligned.m16n8k16.row.col.f32.bf16.bf16.f32 "
        "{%0,%1,%2,%3},{%4,%5,%6,%7},{%8,%9},{%0,%1,%2,%3};"
        : "+f"(d[0]), "+f"(d[1]), "+f"(d[2]), "+f"(d[3])
        : "r"(a[0]), "r"(a[1]), "r"(a[2]), "r"(a[3]), "r"(b[0]), "r"(b[1]));
}

__device__ __forceinline__ void tree_barrier(unsigned* bar, int bid, int tid,
                                             unsigned step1, unsigned perCtr) {
    if (tid == 0) atomicAdd(&bar[(bid & 7) * 32], 1u);
    if (tid < 8) {
        unsigned tgt = step1 * perCtr;
        while (*(volatile unsigned*)&bar[tid * 32] < tgt) {}
    }
    __syncthreads();
}

// ---- bf16 split stores ----
__device__ __forceinline__ void split_store_pair(unsigned char* st, int nCh, int blk,
                                                 int row, int kp, float v0, float v1) {
    int chunk = kp >> 6, kin = kp & 63;
    size_t base = ((size_t)(blk * nCh + chunk)) * PAIR_BYTES;
    unsigned so = swz((unsigned)(row * 128 + kin * 2));
    __nv_bfloat16 h0 = __float2bfloat16(v0), h1 = __float2bfloat16(v1);
    __nv_bfloat16 l0 = __float2bfloat16(v0 - __bfloat162float(h0));
    __nv_bfloat16 l1 = __float2bfloat16(v1 - __bfloat162float(h1));
    *(unsigned*)(st + base + so) =
        (unsigned)__bfloat16_as_ushort(h0) | ((unsigned)__bfloat16_as_ushort(h1) << 16);
    *(unsigned*)(st + base + TILE_BYTES + so) =
        (unsigned)__bfloat16_as_ushort(l0) | ((unsigned)__bfloat16_as_ushort(l1) << 16);
}
__device__ __forceinline__ void split_store_half(unsigned char* tileBase, int row, int kin,
                                                 float v) {
    unsigned so = swz((unsigned)(row * 128 + kin * 2));
    __nv_bfloat16 hi = __float2bfloat16(v);
    __nv_bfloat16 lo = __float2bfloat16(v - __bfloat162float(hi));
    *(unsigned short*)(tileBase + so) = __bfloat16_as_ushort(hi);
    *(unsigned short*)(tileBase + TILE_BYTES + so) = __bfloat16_as_ushort(lo);
}

// ---- prep ----
__device__ __forceinline__ void pack_region(const float* Wh, float* out, int H, long r) {
    long per = 4L * H * H;
    int dir = (int)(r / per);
    long s = r % per;
    int g = (int)(s & 3), jj = (int)((s >> 2) % H), k = (int)(s / (4 * H));
    out[dir * per + s] = Wh[dir * per + (size_t)(g * H + jj) * H + k];
}
#define R_SWH 524288L
#define R_DWS 2097152L
#define R_WB 2097152L
#define R_BW0 1179648L
#define R_BW1 2097152L
#define R_BQ 262144L
#define R_BDEC 3276800L
#define R_CEMB 131072L
#define R_PAD 131072L
#define R_BS0 327680L
#define R_BS1 524288L
#define R_EMBS 81920L
#define R_DLAB 262144L
#define R_CLS 15360L
#define PREP_BLOCKS 52860

__global__ void prep_kernel(const float* __restrict__ sWh0, const float* __restrict__ sWh1,
                            const float* __restrict__ wWh0, const float* __restrict__ wWh1,
                            const float* __restrict__ dWh, const float* __restrict__ wWx0,
                            const float* __restrict__ wWx1, const float* __restrict__ Wq,
                            const float* __restrict__ dWx, const int* __restrict__ words,
                            const float* __restrict__ char_table, const int* __restrict__ sents,
                            const float* __restrict__ word_embs, const int* __restrict__ labels,
                            const float* __restrict__ clsW, const float* __restrict__ sWx0,
                            const float* __restrict__ sWx1) {
    if (blockIdx.x == 0 && threadIdx.x < 8) {
        g_barT[threadIdx.x * 32] = 0u;
        g_barT2[threadIdx.x * 32] = 0u;
        g_barT3[threadIdx.x * 32] = 0u;
    }
    long idx = (long)blockIdx.x * 256 + threadIdx.x;
    if (idx < R_SWH) { pack_region(sWh0, g_sWh0P, SH_, idx); return; }
    idx -= R_SWH;
    if (idx < R_SWH) { pack_region(sWh1, g_sWh1P, SH_, idx); return; }
    idx -= R_SWH;
    if (idx < R_DWS) {
        int n = (int)(idx / 512), kp = 2 * (int)(idx % 512);
        split_store_pair(g_stDWr, 16, n >> 7, n & 127, kp,
                         dWh[(size_t)n * 1024 + kp], dWh[(size_t)n * 1024 + kp + 1]);
        return;
    }
    idx -= R_DWS;
    if (idx < R_WB) {
        int ld = (int)(idx >> 19);
        long e = idx & ((1L << 19) - 1);
        int r = (int)(e >> 8);
        int kp = 2 * (int)(e & 255);
        int g = r & 3, j = r >> 2;
        const float* Ws = (ld >> 1) ? wWh1 : wWh0;
        const float* w = Ws + (size_t)(ld & 1) * 4 * 512 * 512 + (size_t)(g * 512 + j) * 512;
        split_store_pair(g_stWw + (size_t)ld * 16 * 8 * PAIR_BYTES, 8, r >> 7, r & 127, kp,
                         w[kp], w[kp + 1]);
        return;
    }
    idx -= R_WB;
    if (idx < R_BW0) {
        int n = (int)(idx / 288), kp = 2 * (int)(idx % 288);
        float v0 = (kp < 544) ? wWx0[(size_t)n * 544 + kp] : 0.f;
        float v1 = (kp + 1 < 544) ? wWx0[(size_t)n * 544 + kp + 1] : 0.f;
        split_store_pair(g_stB_w0, NCH_W0, n >> 7, n & 127, kp, v0, v1);
        return;
    }
    idx -= R_BW0;
    if (idx < R_BW1) {
        int n = (int)(idx / 512), kp = 2 * (int)(idx % 512);
        split_store_pair(g_stB_w1, NCH_W1, n >> 7, n & 127, kp,
                         wWx1[(size_t)n * 1024 + kp], wWx1[(size_t)n * 1024 + kp + 1]);
        return;
    }
    idx -= R_BW1;
    if (idx < R_BQ) {
        int n = (int)(idx / 512), kp = 2 * (int)(idx % 512);
        split_store_pair(g_stB_q, NCH_Q, n >> 7, n & 127, kp,
                         Wq[(size_t)kp * 512 + n], Wq[(size_t)(kp + 1) * 512 + n]);
        return;
    }
    idx -= R_BQ;
    if (idx < R_BDEC) {
        int n = (int)(idx / 800), kp = 2 * (int)(idx % 800);
        float v0 = (kp < 1544) ? dWx[(size_t)n * 1544 + kp] : 0.f;
        float v1 = (kp + 1 < 1544) ? dWx[(size_t)n * 1544 + kp + 1] : 0.f;
        split_store_pair(g_stB_dec, NCH_DEC, n >> 7, n & 127, kp, v0, v1);
        return;
    }
    idx -= R_BDEC;
    if (idx < R_CEMB) {
        int r = (int)(idx / 16), kp = 2 * (int)(idx % 16);
        int w = words[r];
        split_store_pair(g_stageA, NCH_W0, r >> 7, r & 127, kp,
                         char_table[w * 32 + kp], char_table[w * 32 + kp + 1]);
        return;
    }
    idx -= R_CEMB;
    if (idx < R_PAD) {
        int r = (int)(idx / 16), kp = 544 + 2 * (int)(idx % 16);
        split_store_pair(g_stageA, NCH_W0, r >> 7, r & 127, kp, 0.f, 0.f);
        return;
    }
    idx -= R_PAD;
    if (idx < R_BS0) {
        int n = (int)(idx / 160), kp = 2 * (int)(idx % 160);
        int dir = n >> 10, j = n & 1023;
        const float* w = sWx0 + (size_t)dir * 1024 * 300 + (size_t)j * 300;
        float v0 = (kp < 300) ? w[kp] : 0.f;
        float v1 = (kp + 1 < 300) ? w[kp + 1] : 0.f;
        split_store_pair(g_stB_s0, 5, n >> 7, n & 127, kp, v0, v1);
        return;
    }
    idx -= R_BS0;
    if (idx < R_BS1) {
        int n = (int)(idx / 256), kp = 2 * (int)(idx % 256);
        int dir = n >> 10, j = n & 1023;
        const float* w = sWx1 + (size_t)dir * 1024 * 512 + (size_t)j * 512;
        split_store_pair(g_stB_s1, 8, n >> 7, n & 127, kp, w[kp], w[kp + 1]);
        return;
    }
    idx -= R_BS1;
    if (idx < R_EMBS) {
        int r = (int)(idx / 160), kp = 2 * (int)(idx % 160);
        const float* e = word_embs + (size_t)sents[r] * 300;
        float v0 = (kp < 300) ? e[kp] : 0.f;
        float v1 = (kp + 1 < 300) ? e[kp + 1] : 0.f;
        split_store_pair(g_stageS, 5, r >> 7, r & 127, kp, v0, v1);
        return;
    }
    idx -= R_EMBS;
    if (idx < R_DLAB) {
        int r = (int)(idx / 32), kp = 1536 + 2 * (int)(idx % 32);
        float v0 = (kp < 1544) ? (float)labels[r * 8 + (kp - 1536)] : 0.f;
        float v1 = (kp + 1 < 1544) ? (float)labels[r * 8 + (kp + 1 - 1536)] : 0.f;
        split_store_pair(g_stageD, NCH_DEC, r >> 7, r & 127, kp, v0, v1);
        return;
    }
    idx -= R_DLAB;
    if (idx < R_CLS) {
        int n = (int)(idx / 1024), k = (int)(idx % 1024);
        g_clsWT[n * 1024 + k] = clsW[(size_t)k * 15 + n];
    }
}

// ---- HMMA GEMM: 512 threads (16 warps, 32x32 warp tiles), bulk-async 2-stage ----
__global__ void __launch_bounds__(512) tgemm_kernel(
    const unsigned char* __restrict__ stA, const unsigned char* __restrict__ stB,
    const float* __restrict__ bias, float* __restrict__ C, int N, int nCh) {
    extern __shared__ unsigned char smraw[];
    uint32_t smb = smem_u32(smraw);
    uint32_t ab = (smb + 1023) & ~1023u;
    uint32_t ctrl = ab + 131072;
    int tid = threadIdx.x, lane = tid & 31, wid = tid >> 5;
    int wm = wid & 3, wn = wid >> 2;
    int nb = blockIdx.x, mb = blockIdx.y;

    if (tid == 0) {
        mbar_init(ctrl, 1);
        mbar_init(ctrl + 8, 1);
        fence_async();
    }
    __syncthreads();

    float acc[2][4][4];
#pragma unroll
    for (int i = 0; i < 2; ++i)
#pragma unroll
        for (int j = 0; j < 4; ++j)
#pragma unroll
            for (int k = 0; k < 4; ++k) acc[i][j][k] = 0.f;

    int ar = (lane & 7) + ((lane >> 3) & 1) * 8;
    int ac = (lane >> 4) * 16;
    int br = (lane & 7) + ((lane >> 4) & 1) * 8;
    int bc = ((lane >> 3) & 1) * 16;

    auto issue = [&](int c) {
        if (tid == 0) {
            uint32_t bar = ctrl + (c & 1) * 8;
            uint32_t dst = ab + (c & 1) * 65536;
            mbar_expect_tx(bar, 65536u);
            cp_bulk(dst, stA + ((size_t)mb * nCh + c) * PAIR_BYTES, 32768u, bar);
            cp_bulk(dst + 32768, stB + ((size_t)nb * nCh + c) * PAIR_BYTES, 32768u, bar);
        }
    };

    issue(0);
    if (nCh > 1) issue(1);
    for (int c = 0; c < nCh; ++c) {
        int buf = c & 1;
        mbar_wait(ctrl + buf * 8, (c >> 1) & 1);
        uint32_t base = ab + buf * 65536;
#pragma unroll
        for (int ks = 0; ks < 4; ++ks) {
            uint32_t ah[2][4], al[2][4], bh[2][4], bl[2][4];
#pragma unroll
            for (int mf = 0; mf < 2; ++mf) {
                uint32_t off = swz((unsigned)((wm * 32 + mf * 16 + ar) * 128 + ac + ks * 32));
                ldm_x4(ah[mf], base + off);
                ldm_x4(al[mf], base + 16384 + off);
            }
#pragma unroll
            for (int nf2 = 0; nf2 < 2; ++nf2) {
                uint32_t off = swz((unsigned)((wn * 32 + nf2 * 16 + br) * 128 + bc + ks * 32));
                ldm_x4(bh[nf2], base + 32768 + off);
                ldm_x4(bl[nf2], base + 49152 + off);
            }
#pragma unroll
            for (int mf = 0; mf < 2; ++mf)
#pragma unroll
                for (int nf = 0; nf < 4; ++nf) {
                    mma16816(acc[mf][nf], ah[mf], &bh[nf >> 1][(nf & 1) * 2]);
                    mma16816(acc[mf][nf], ah[mf], &bl[nf >> 1][(nf & 1) * 2]);
                    mma16816(acc[mf][nf], al[mf], &bh[nf >> 1][(nf & 1) * 2]);
                }
        }
        __syncthreads();
        if (c + 2 < nCh) issue(c + 2);
    }
#pragma unroll
    for (int mf = 0; mf < 2; ++mf) {
#pragma unroll
        for (int nf = 0; nf < 4; ++nf) {
            int row = mb * 128 + wm * 32 + mf * 16 + (lane >> 2);
            int col = nb * 128 + wn * 32 + nf * 8 + (lane & 3) * 2;
            float b0 = bias ? bias[col] : 0.f;
            float b1 = bias ? bias[col + 1] : 0.f;
            float2 v0 = make_float2(acc[mf][nf][0] + b0, acc[mf][nf][1] + b1);
            float2 v1 = make_float2(acc[mf][nf][2] + b0, acc[mf][nf][3] + b1);
            *(float2*)(C + (size_t)row * N + col) = v0;
            *(float2*)(C + (size_t)(row + 8) * N + col) = v1;
        }
    }
}

// ---- persistent HMMA word-LSTM recurrence ----
__global__ void __launch_bounds__(256) wordrec_kernel(
    const unsigned char* __restrict__ stW, const float* __restrict__ pre,
    int writeDec, int base) {
    extern __shared__ unsigned char dsm[];
    uint32_t smb = smem_u32(dsm);
    int tid = threadIdx.x, lane = tid & 31, wid = tid >> 5;
    int wm = wid & 1, wn = wid >> 1;
    int bid = blockIdx.x;
    int dir = bid >> 6, r6 = bid & 63, mb = r6 >> 4, nt = r6 & 15;

    {
        const unsigned char* wb = stW + ((size_t)(dir * 16 + nt)) * 8 * PAIR_BYTES;
        uint4* dst = (uint4*)dsm;
#pragma unroll 4
        for (int i = tid; i < 8192; i += 256) {
            int c = i >> 10, w = i & 1023;
            dst[i] = *(const uint4*)(wb + (size_t)c * PAIR_BYTES + w * 16);
        }
    }
    __syncthreads();

    int ar = (lane & 7) + ((lane >> 3) & 1) * 8;
    int ac = (lane >> 4) * 16;
    int br = (lane & 7) + ((lane >> 4) & 1) * 8;
    int bc = ((lane >> 3) & 1) * 16;

    float cacc[4][4][2];
#pragma unroll
    for (int a = 0; a < 4; ++a)
#pragma unroll
        for (int b = 0; b < 4; ++b) { cacc[a][b][0] = 0.f; cacc[a][b][1] = 0.f; }

    for (int t = 0; t < 16; ++t) {
        int rb = t & 1, wbuf = rb ^ 1;
        int tdir = dir ? (15 - t) : t;

        auto issueW = [&](int c) {
            uint32_t dst = smb + 131072 + (c & 1) * 49152;
            const unsigned char* aSrc =
                g_hstage + (((size_t)((dir * 2 + rb) * 4 + mb)) * 8 + c) * PAIR_BYTES;
            const unsigned char* bSrc =
                stW + (((size_t)(dir * 16 + nt)) * 8 + c) * PAIR_BYTES + TILE_BYTES;
#pragma unroll
            for (int i = 0; i < 8; ++i)
                cp_async16(dst + (tid + i * 256) * 16, aSrc + (tid + i * 256) * 16);
#pragma unroll
            for (int i = 0; i < 4; ++i)
                cp_async16(dst + 32768 + (tid + i * 256) * 16, bSrc + (tid + i * 256) * 16);
            cp_commit();
        };

        float acc[4][4][4];
#pragma unroll
        for (int a = 0; a < 4; ++a)
#pragma unroll
            for (int b = 0; b < 4; ++b)
#pragma unroll
                for (int k = 0; k < 4; ++k) acc[a][b][k] = 0.f;

        if (t > 0) {
            issueW(0);
            for (int c = 0; c < 8; ++c) {
                if (c + 1 < 8) { issueW(c + 1); cp_wait<1>(); }
                else           { cp_wait<0>(); }
                __syncthreads();
                uint32_t sb = smb + 131072 + (c & 1) * 49152;
                uint32_t bhb = smb + c * 16384;
#pragma unroll
                for (int ks = 0; ks < 4; ++ks) {
                    uint32_t ah[4][4], al[4][4], bh[2][4], bl[2][4];
#pragma unroll
                    for (int mf = 0; mf < 4; ++mf) {
                        uint32_t off = swz((unsigned)((wm * 64 + mf * 16 + ar) * 128 + ac + ks * 32));
                        ldm_x4(ah[mf], sb + off);
                        ldm_x4(al[mf], sb + 16384 + off);
                    }
#pragma unroll
                    for (int nf2 = 0; nf2 < 2; ++nf2) {
                        uint32_t off = swz((unsigned)((wn * 32 + nf2 * 16 + br) * 128 + bc + ks * 32));
                        ldm_x4(bh[nf2], bhb + off);
                        ldm_x4(bl[nf2], sb + 32768 + off);
                    }
#pragma unroll
                    for (int mf = 0; mf < 4; ++mf)
#pragma unroll
                        for (int nf = 0; nf < 4; ++nf) {
                            mma16816(acc[mf][nf], ah[mf], &bh[nf >> 1][(nf & 1) * 2]);
                            mma16816(acc[mf][nf], ah[mf], &bl[nf >> 1][(nf & 1) * 2]);
                            mma16816(acc[mf][nf], al[mf], &bh[nf >> 1][(nf & 1) * 2]);
                        }
                }
                __syncthreads();
            }
        }

#pragma unroll
        for (int mf = 0; mf < 4; ++mf)
#pragma unroll
            for (int nf = 0; nf < 4; ++nf) {
                float p0 = __shfl_xor_sync(0xffffffffu, acc[mf][nf][0], 1);
                float p1 = __shfl_xor_sync(0xffffffffu, acc[mf][nf][1], 1);
                float p2 = __shfl_xor_sync(0xffffffffu, acc[mf][nf][2], 1);
                float p3 = __shfl_xor_sync(0xffffffffu, acc[mf][nf][3], 1);
                if (!(lane & 1)) {
                    int j = nt * 32 + wn * 8 + nf * 2 + ((lane & 3) >> 1);
                    int r0 = wm * 64 + mf * 16 + (lane >> 2);
#pragma unroll
                    for (int rr = 0; rr < 2; ++rr) {
                        int r = r0 + rr * 8;
                        int n = mb * 128 + r;
                        size_t pb = (size_t)(n * 16 + tdir) * 4096 + dir * 2048 + j;
                        float ai = (rr ? acc[mf][nf][2] : acc[mf][nf][0]) + pre[pb];
                        float af = (rr ? acc[mf][nf][3] : acc[mf][nf][1]) + pre[pb + 512];
                        float ag = (rr ? p2 : p0) + pre[pb + 1024];
                        float ao = (rr ? p3 : p1) + pre[pb + 1536];
                        float cv = cacc[mf][nf][rr];
                        cv = sigm(af) * cv + sigm(ai) * tanhf(ag);
                        float hn = sigm(ao) * tanhf(cv);
                        cacc[mf][nf][rr] = cv;
                        split_store_half(
                            g_hstage + (((size_t)((dir * 2 + wbuf) * 4 + mb)) * 8 + (j >> 6)) * PAIR_BYTES,
                            r, j & 63, hn);
                        int rA = n * 16 + tdir, kp = dir * 512 + j;
                        split_store_half(
                            g_stageA + (((size_t)(rA >> 7) * 16 + (kp >> 6))) * PAIR_BYTES,
                            rA & 127, kp & 63, hn);
                        if (writeDec) {
                            int kp2 = 512 + kp;
                            split_store_half(
                                g_stageD + (((size_t)(rA >> 7) * 25 + (kp2 >> 6))) * PAIR_BYTES,
                                rA & 127, kp2 & 63, hn);
                        }
                    }
                }
            }
        __threadfence();
        __syncthreads();
        tree_barrier(g_barT2, bid, tid, (unsigned)(base + t + 1), 16u);
    }
}

// ---- persistent HMMA decoder ----
__global__ void __launch_bounds__(256) dec_persist_kernel(
    const float* __restrict__ pre, float* __restrict__ dout) {
    extern __shared__ unsigned char dsm[];
    uint32_t smb = smem_u32(dsm);
    int tid = threadIdx.x, lane = tid & 31, w = tid >> 5;
    int bid = blockIdx.x;
    {
        const uint4* src = (const uint4*)g_stDWr;
        uint4* dst = (uint4*)dsm;
#pragma unroll 4
        for (int it = 0; it < 32; ++it) {
            int flat = tid + it * 256;
            int q = flat & 7;
            int ru = flat >> 3;
            int i = ru & 7;
            int hl = (ru >> 3) & 1;
            int g = (ru >> 4) & 3;
            int c = ru >> 6;
            size_t sb = ((((size_t)(g * 8 + (bid >> 4)) * 16 + c) * PAIR_BYTES
                         + (size_t)hl * TILE_BYTES
                         + (size_t)((bid & 15) * 8 + i) * 128) >> 4) + q;
            int db = ((c * 8192 + hl * 4096 + (g * 8 + i) * 128) >> 4) + q;
            dst[db] = src[sb];
        }
    }
    __syncthreads();

    float* red = (float*)(dsm + 131072);
    const unsigned* hHr[2] = {(const unsigned*)&g_hsplitH[0][0], (const unsigned*)&g_hsplitH[1][0]};
    const unsigned* hLr[2] = {(const unsigned*)&g_hsplitL[0][0], (const unsigned*)&g_hsplitL[1][0]};

    int bb = tid >> 3, hh = tid & 7;
    int j = bid * 8 + hh;
    float cc = 0.f;

    int br = (lane & 7) + ((lane >> 4) & 1) * 8;
    int bc = ((lane >> 3) & 1) * 16;
    int k0base = w * 128;

    for (int t = 0; t < 256; ++t) {
        int rb = t & 1;
        const float* p = pre + ((size_t)bb * 256 + t) * 4096 + j;
        float px0 = p[0], px1 = p[1024], px2 = p[2048], px3 = p[3072];

        float acc[2][4][4];
#pragma unroll
        for (int m = 0; m < 2; ++m)
#pragma unroll
            for (int g = 0; g < 4; ++g)
#pragma unroll
                for (int r4 = 0; r4 < 4; ++r4) acc[m][g][r4] = 0.f;

        if (t > 0) {
#pragma unroll 2
            for (int kf = 0; kf < 8; ++kf) {
                int k0 = k0base + kf * 16;
                uint32_t ah[2][4], al[2][4];
#pragma unroll
                for (int m = 0; m < 2; ++m) {
                    int base2 = ((m * 16 + (lane >> 2)) * 1024 + k0) / 2 + (lane & 3);
                    ah[m][0] = __ldcg(hHr[rb] + base2);
                    ah[m][1] = __ldcg(hHr[rb] + base2 + 4096);
                    ah[m][2] = __ldcg(hHr[rb] + base2 + 4);
                    ah[m][3] = __ldcg(hHr[rb] + base2 + 4100);
                    al[m][0] = __ldcg(hLr[rb] + base2);
                    al[m][1] = __ldcg(hLr[rb] + base2 + 4096);
                    al[m][2] = __ldcg(hLr[rb] + base2 + 4);
                    al[m][3] = __ldcg(hLr[rb] + base2 + 4100);
                }
                int chunk = k0 >> 6, kin = k0 & 63;
                uint32_t cbs = smb + chunk * 8192;
                uint32_t bh[2][4], bl[2][4];
#pragma unroll
                for (int nt = 0; nt < 2; ++nt) {
                    uint32_t off = swz((unsigned)((nt * 16 + br) * 128 + bc + kin * 2));
                    ldm_x4(bh[nt], cbs + off);
                    ldm_x4(bl[nt], cbs + 4096 + off);
                }
#pragma unroll
                for (int m = 0; m < 2; ++m)
#pragma unroll
                    for (int g = 0; g < 4; ++g) {
                        mma16816(acc[m][g], ah[m], &bh[g >> 1][(g & 1) * 2]);
                        mma16816(acc[m][g], ah[m], &bl[g >> 1][(g & 1) * 2]);
                        mma16816(acc[m][g], al[m], &bh[g >> 1][(g & 1) * 2]);
                    }
            }
        }
#pragma unroll
        for (int m = 0; m < 2; ++m)
#pragma unroll
            for (int g = 0; g < 4; ++g)
#pragma unroll
                for (int r4 = 0; r4 < 4; ++r4)
                    red[((w * 2 + m) * 4 + g) * 128 + lane * 4 + r4] = acc[m][g][r4];
        __syncthreads();
        {
            int r = bb & 15, m = bb >> 4;
            int gl = ((r & 7) << 2) | (hh >> 1);
            int rg = (hh & 1) + 2 * ((r >> 3) & 1);
            float gv[4] = {0.f, 0.f, 0.f, 0.f};
#pragma unroll
            for (int w2 = 0; w2 < 8; ++w2)
#pragma unroll
                for (int g = 0; g < 4; ++g)
                    gv[g] += red[((w2 * 2 + m) * 4 + g) * 128 + gl * 4 + rg];
            float ai = gv[0] + px0;
            float af = gv[1] + px1;
            float agg = gv[2] + px2;
            float ao = gv[3] + px3;
            cc = sigm(af) * cc + sigm(ai) * tanhf(agg);
            float hn = sigm(ao) * tanhf(cc);
            dout[((size_t)bb * 256 + t) * 1024 + j] = hn;
            __nv_bfloat16 hi = __float2bfloat16(hn);
            __nv_bfloat16 lo = __float2bfloat16(hn - __bfloat162float(hi));
            g_hsplitH[rb ^ 1][bb * 1024 + j] = hi;
            g_hsplitL[rb ^ 1][bb * 1024 + j] = lo;
        }
        __threadfence();
        __syncthreads();
        tree_barrier(g_barT, bid, tid, (unsigned)(t + 1), 16u);
    }
}

// ---- persistent sentence BiLSTM recurrence ----
template <int MODE>
__global__ void __launch_bounds__(256) sentrec_kernel(
    const float* __restrict__ pre, const float* __restrict__ WhP,
    float* __restrict__ out, const int* __restrict__ words, int base) {
    extern __shared__ unsigned char sms[];
    float4* wS = (float4*)sms;
    float* hsm = (float*)(sms + 65536);
    float* wm = (float*)(sms + 65536 + 16384);
    int tid = threadIdx.x, bid = blockIdx.x;
    int dir = bid >> 5, jb = (bid >> 1) & 15, sb = bid & 1;
    int jl = tid & 15, sq = tid >> 4;
    int s = sb * 16 + sq;
    int j = jb * 16 + jl;

    const float4* Wsrc = (const float4*)(WhP + (size_t)dir * (256 * 256 * 4));
    for (int i = tid; i < 4096; i += 256) {
        int k = i >> 4;
        wS[i] = Wsrc[k * 256 + jb * 16 + (i & 15)];
    }
    if (MODE == 1) {
        for (int x = tid; x < 4096; x += 256)
            wm[x] = (words[(sb * 16 + (x >> 8)) * 256 + (x & 255)] != 0) ? 1.f : 0.f;
    }
    float cc = 0.f;
    __syncthreads();

    for (int tt = 0; tt < 16; ++tt) {
        int rb = tt & 1;
        int t = dir ? (15 - tt) : tt;
        if (tt > 0) {
            const float4* src = (const float4*)(g_shs + ((rb * 2 + dir) * 32 + sb * 16) * 256);
            float4* dst = (float4*)hsm;
#pragma unroll
            for (int i = 0; i < 4; ++i) dst[tid + i * 256] = __ldcg(src + tid + i * 256);
            __syncthreads();
        }
        size_t pb = ((size_t)(s * 16 + t) * 2 + dir) * 1024 + j;
        float ai = pre[pb], af = pre[pb + 256], ag = pre[pb + 512], ao = pre[pb + 768];
        if (tt > 0) {
#pragma unroll 8
            for (int k = 0; k < 256; ++k) {
                float4 w = wS[k * 16 + jl];
                float hk = hsm[sq * 256 + k];
                ai += hk * w.x; af += hk * w.y; ag += hk * w.z; ao += hk * w.w;
            }
        }
        float cv = sigm(af) * cc + sigm(ai) * tanhf(ag);
        float hn = sigm(ao) * tanhf(cv);
        cc = cv;
        g_shs[(((rb ^ 1) * 2 + dir) * 32 + s) * 256 + j] = hn;
        if (MODE == 0) {
            int r = s * 16 + t, kp = dir * 256 + j;
            split_store_half(g_stageS2 + ((size_t)((r >> 7) * 8 + (kp >> 6))) * PAIR_BYTES,
                             r & 127, kp & 63, hn);
        } else {
            out[((size_t)s * 16 + t) * 512 + dir * 256 + j] = hn;
            float v1 = __shfl_down_sync(0xffffffffu, hn, 1);
            if (!(jl & 1)) {
                int kp = 32 + dir * 256 + j;
                int rbrow = (s * 16 + t) * 16;
                int blk = rbrow >> 7;
#pragma unroll
                for (int tw = 0; tw < 16; ++tw) {
                    float m = wm[sq * 256 + t * 16 + tw];
                    split_store_pair(g_stageA, NCH_W0, blk, (rbrow & 127) + tw, kp, hn * m, v1 * m);
                }
            }
        }
        __threadfence();
        __syncthreads();
        tree_barrier(g_barT3, bid, tid, (unsigned)(base + tt + 1), 8u);
    }
}

// ---- attention ----
__global__ void attention_kernel(const float* __restrict__ q, const float* __restrict__ sent_enc,
                                 const int* __restrict__ words, float* __restrict__ map_out) {
    int bi = blockIdx.x, b = bi >> 4, i = bi & 15;
    __shared__ float se[16 * 513];
    __shared__ float sc[16][16];
    __shared__ float mp[16][16];
    __shared__ int kv[16];
    for (int x = threadIdx.x; x < 16 * 512; x += 256) {
        int jj = x >> 9, d = x & 511;
        se[jj * 513 + d] = sent_enc[((size_t)b * 16 + jj) * 512 + d];
    }
    if (threadIdx.x < 16) {
        int jj = threadIdx.x, any = 0;
        for (int tw = 0; tw < 16; ++tw) any |= (words[(b * 16 + jj) * 16 + tw] != 0);
        kv[jj] = any;
    }
    __syncthreads();
    {
        int cdx = threadIdx.x >> 4, jj = threadIdx.x & 15;
        const float* qr = q + ((size_t)bi * 16 + cdx) * 512;
        const float* ser = se + jj * 513;
        float s = 0.f;
#pragma unroll 4
        for (int d = 0; d < 512; ++d) s += qr[d] * ser[d];
        sc[cdx][jj] = s;
    }
    __syncthreads();
    if (threadIdx.x < 16) {
        int cdx = threadIdx.x;
        float v[16], m = -1e30f;
#pragma unroll
        for (int jj = 0; jj < 16; ++jj) {
            bool valid = (kv[jj] != 0) && (jj != i);
            v[jj] = valid ? sc[cdx][jj] : -1e9f;
            m = fmaxf(m, v[jj]);
        }
        float sum = 0.f;
#pragma unroll
        for (int jj = 0; jj < 16; ++jj) { v[jj] = expf(v[jj] - m); sum += v[jj]; }
        float inv = 1.f / sum;
#pragma unroll
        for (int jj = 0; jj < 16; ++jj) mp[cdx][jj] = v[jj] * inv;
    }
    __syncthreads();
    if (map_out != nullptr && threadIdx.x < 256) {
        int x = threadIdx.x;
        map_out[(size_t)bi * 256 + x] = mp[x >> 4][x & 15];
    }
    for (int x = threadIdx.x; x < 16 * 512; x += 256) {
        int cdx = x >> 9, d = x & 511;
        float s = 0.f;
#pragma unroll
        for (int jj = 0; jj < 16; ++jj) s += mp[cdx][jj] * se[jj * 513 + d];
        int r = bi * 16 + cdx;
        split_store_half(g_stageD + ((size_t)(r >> 7) * 25 + (d >> 6)) * PAIR_BYTES,
                         r & 127, d & 63, s);
    }
}

// ---- classifier: warp per row ----
__global__ void __launch_bounds__(256) classifier_kernel(
    const float* __restrict__ dec_out, const float* __restrict__ Wt,
    const float* __restrict__ bias, float* __restrict__ out) {
    __shared__ float res[8][16];
    int w = threadIdx.x >> 5, lane = threadIdx.x & 31;
    int m = blockIdx.x * 8 + w;
    const float4* x4 = (const float4*)(dec_out + (size_t)m * 1024);
    float4 xv[8];
#pragma unroll
    for (int i = 0; i < 8; ++i) xv[i] = x4[lane + i * 32];
#pragma unroll
    for (int n = 0; n < 15; ++n) {
        const float4* w4 = (const float4*)(Wt + n * 1024);
        float s = 0.f;
#pragma unroll
        for (int i = 0; i < 8; ++i) {
            float4 b = w4[lane + i * 32];
            s += xv[i].x * b.x + xv[i].y * b.y + xv[i].z * b.z + xv[i].w * b.w;
        }
#pragma unroll
        for (int o = 16; o; o >>= 1) s += __shfl_xor_sync(0xffffffffu, s, o);
        if (lane == 0) res[w][n] = s + bias[n];
    }
    __syncthreads();
    for (int i = threadIdx.x; i < 120; i += 256) {
        int mr = i / 15, n = i % 15;
        out[(size_t)(blockIdx.x * 8 + mr) * 15 + n] = res[mr][n];
    }
}

// ---- host ----
static void* symp(const void* s) { void* p = nullptr; cudaGetSymbolAddress(&p, s); return p; }

extern "C" void kernel_launch(void* const* d_in, const int* in_sizes, int n_in,
                              void* d_out, int out_size) {
    (void)in_sizes; (void)n_in;
    const int* sents = (const int*)d_in[0];
    const int* words = (const int*)d_in[1];
    const int* labels = (const int*)d_in[2];
    const float* word_embs = (const float*)d_in[3];
    const float* char_table = (const float*)d_in[4];
    const float* sWx0 = (const float*)d_in[5];
    const float* sWh0 = (const float*)d_in[6];
    const float* sb0 = (const float*)d_in[7];
    const float* sWx1 = (const float*)d_in[8];
    const float* sWh1 = (const float*)d_in[9];
    const float* sb1 = (const float*)d_in[10];
    const float* wWx0 = (const float*)d_in[11];
    const float* wWh0 = (const float*)d_in[12];
    const float* wb0 = (const float*)d_in[13];
    const float* wWx1 = (const float*)d_in[14];
    const float* wWh1 = (const float*)d_in[15];
    const float* wb1 = (const float*)d_in[16];
    const float* Wq = (const float*)d_in[17];
    const float* dWx = (const float*)d_in[18];
    const float* dWh = (const float*)d_in[19];
    const float* db = (const float*)d_in[20];
    const float* clsW = (const float*)d_in[21];
    const float* clsb = (const float*)d_in[22];
    float* out = (float*)d_out;

    float* pre_s = (float*)symp(g_pre_s);
    float* sent_enc = (float*)symp(g_sent_enc);
    float* pre_w = (float*)symp(g_pre_w);
    float* qbuf = (float*)symp(g_q);
    float* pre_d = (float*)symp(g_pre_d);
    float* dec_out = (float*)symp(g_dec_out);
    float* sWh0P = (float*)symp(g_sWh0P);
    float* sWh1P = (float*)symp(g_sWh1P);
    float* clsWT = (float*)symp(g_clsWT);
    const unsigned char* stA = (const unsigned char*)symp(g_stageA);
    const unsigned char* stD = (const unsigned char*)symp(g_stageD);
    const unsigned char* stS = (const unsigned char*)symp(g_stageS);
    const unsigned char* stS2 = (const unsigned char*)symp(g_stageS2);
    const unsigned char* stBs0 = (const unsigned char*)symp(g_stB_s0);
    const unsigned char* stBs1 = (const unsigned char*)symp(g_stB_s1);
    const unsigned char* stBw0 = (const unsigned char*)symp(g_stB_w0);
    const unsigned char* stBw1 = (const unsigned char*)symp(g_stB_w1);
    const unsigned char* stBq = (const unsigned char*)symp(g_stB_q);
    const unsigned char* stBdec = (const unsigned char*)symp(g_stB_dec);
    const unsigned char* stWw = (const unsigned char*)symp(g_stWw);

    cudaFuncSetAttribute(tgemm_kernel, cudaFuncAttributeMaxDynamicSharedMemorySize, TG_SMEM);
    cudaFuncSetAttribute(dec_persist_kernel, cudaFuncAttributeMaxDynamicSharedMemorySize, DEC_SMEM);
    cudaFuncSetAttribute(wordrec_kernel, cudaFuncAttributeMaxDynamicSharedMemorySize, WR_SMEM);
    cudaFuncSetAttribute(sentrec_kernel<0>, cudaFuncAttributeMaxDynamicSharedMemorySize, SR_SMEM);
    cudaFuncSetAttribute(sentrec_kernel<1>, cudaFuncAttributeMaxDynamicSharedMemorySize, SR_SMEM);

    const size_t wwLayer = 2ul * 16 * 8 * PAIR_BYTES;

    prep_kernel<<<PREP_BLOCKS, 256>>>(sWh0, sWh1, wWh0, wWh1, dWh, wWx0, wWx1, Wq, dWx,
                                      words, char_table, sents, word_embs, labels, clsW,
                                      sWx0, sWx1);
    tgemm_kernel<<<dim3(16, 4), 512, TG_SMEM>>>(stS, stBs0, sb0, pre_s, 2048, 5);
    sentrec_kernel<0><<<64, 256, SR_SMEM>>>(pre_s, sWh0P, nullptr, nullptr, 0);
    tgemm_kernel<<<dim3(16, 4), 512, TG_SMEM>>>(stS2, stBs1, sb1, pre_s, 2048, 8);
    sentrec_kernel<1><<<64, 256, SR_SMEM>>>(pre_s, sWh1P, sent_enc, words, 16);
    tgemm_kernel<<<dim3(32, 64), 512, TG_SMEM>>>(stA, stBw0, wb0, pre_w, 4096, NCH_W0);
    wordrec_kernel<<<128, 256, WR_SMEM>>>(stWw, pre_w, 0, 0);
    tgemm_kernel<<<dim3(32, 64), 512, TG_SMEM>>>(stA, stBw1, wb1, pre_w, 4096, NCH_W1);
    wordrec_kernel<<<128, 256, WR_SMEM>>>(stWw + wwLayer, pre_w, 1, 16);
    tgemm_kernel<<<dim3(4, 64), 512, TG_SMEM>>>(stA, stBq, nullptr, qbuf, 512, NCH_Q);
    float* map_out = (out_size >= (NR_ * 15 + 131072)) ? (out + NR_ * 15) : nullptr;
    attention_kernel<<<NSEQ_, 256>>>(qbuf, sent_enc, words, map_out);
    tgemm_kernel<<<dim3(32, 64), 512, TG_SMEM>>>(stD, stBdec, db, pre_d, 4096, NCH_DEC);
    dec_persist_kernel<<<128, 256, DEC_SMEM>>>(pre_d, dec_out);
    classifier_kernel<<<NR_ / 8, 256>>>(dec_out, clsWT, clsb, out);
}

// round 14
// speedup vs baseline: 1.0013x; 1.0013x over previous
#include <cuda_runtime.h>
#include <cuda_bf16.h>
#include <math.h>
#include <stdint.h>

#define B_ 32
#define SH_ 256
#define WH_ 512
#define DH_ 1024
#define NSEQ_ 512
#define NR_ 8192
#define NCH_W0 9
#define NCH_W1 16
#define NCH_Q 16
#define NCH_DEC 25
#define TILE_BYTES 16384
#define PAIR_BYTES 32768
#define TG_SMEM 197696
#define DEC_SMEM (131072 + 32768)
#define WR_SMEM (131072 + 2 * 49152 + 64)
#define SR_SMEM (65536 + 16384 + 16384)

#define DEVBUF __device__ __align__(16)
DEVBUF float g_pre_s[NSEQ_ * 2048];
DEVBUF float g_sent_enc[NSEQ_ * 512];
DEVBUF float g_pre_w[NR_ * 4096];
DEVBUF float g_q[NR_ * 512];
DEVBUF float g_pre_d[NR_ * 4096];
DEVBUF float g_dec_out[NR_ * 1024];
DEVBUF float g_sWh0P[2 * SH_ * SH_ * 4];
DEVBUF float g_sWh1P[2 * SH_ * SH_ * 4];
DEVBUF float g_clsWT[15 * 1024];
DEVBUF float g_shs[2 * 2 * 32 * 256];
DEVBUF unsigned char g_stageA[64ul * 16 * PAIR_BYTES];
DEVBUF unsigned char g_stageD[64ul * 25 * PAIR_BYTES];
DEVBUF unsigned char g_stageS[4ul * 5 * PAIR_BYTES];
DEVBUF unsigned char g_stageS2[4ul * 8 * PAIR_BYTES];
DEVBUF unsigned char g_stB_s0[16ul * 5 * PAIR_BYTES];
DEVBUF unsigned char g_stB_s1[16ul * 8 * PAIR_BYTES];
DEVBUF unsigned char g_stB_w0[32ul * NCH_W0 * PAIR_BYTES];
DEVBUF unsigned char g_stB_w1[32ul * NCH_W1 * PAIR_BYTES];
DEVBUF unsigned char g_stB_q[4ul * NCH_Q * PAIR_BYTES];
DEVBUF unsigned char g_stB_dec[32ul * NCH_DEC * PAIR_BYTES];
DEVBUF unsigned char g_stDWr[32ul * 16 * PAIR_BYTES];
DEVBUF unsigned char g_stWw[4ul * 16 * 8 * PAIR_BYTES];
DEVBUF unsigned char g_hstage[128ul * PAIR_BYTES];
DEVBUF __nv_bfloat16 g_hsplitH[2][B_ * DH_];
DEVBUF __nv_bfloat16 g_hsplitL[2][B_ * DH_];
DEVBUF unsigned g_barT[8 * 32];
DEVBUF unsigned g_barT2[8 * 32];
DEVBUF unsigned g_barT3[8 * 32];

__device__ __forceinline__ float sigm(float x) { return 1.f / (1.f + expf(-x)); }
__device__ __forceinline__ unsigned swz(unsigned o) { return o ^ ((o >> 3) & 0x70); }

__device__ __forceinline__ uint32_t smem_u32(const void* p) {
    uint32_t a;
    asm("{ .reg .u64 t; cvta.to.shared.u64 t, %1; cvt.u32.u64 %0, t; }" : "=r"(a) : "l"(p));
    return a;
}
__device__ __forceinline__ void cp_bulk(uint32_t dst, const void* src, uint32_t bytes,
                                        uint32_t mbar) {
    asm volatile(
        "cp.async.bulk.shared::cta.global.mbarrier::complete_tx::bytes [%0], [%1], %2, [%3];"
        :: "r"(dst), "l"(src), "r"(bytes), "r"(mbar) : "memory");
}
__device__ __forceinline__ void mbar_init(uint32_t a, uint32_t c) {
    asm volatile("mbarrier.init.shared.b64 [%0], %1;" :: "r"(a), "r"(c) : "memory");
}
__device__ __forceinline__ void mbar_expect_tx(uint32_t a, uint32_t bytes) {
    asm volatile("mbarrier.arrive.expect_tx.shared.b64 _, [%0], %1;"
                 :: "r"(a), "r"(bytes) : "memory");
}
__device__ __forceinline__ void mbar_wait(uint32_t a, uint32_t par) {
    asm volatile(
        "{\n\t.reg .pred P1;\n\tLW%=:\n\t"
        "mbarrier.try_wait.parity.acquire.cta.shared::cta.b64 P1, [%0], %1, 0x989680;\n\t"
        "@P1 bra.uni LD%=;\n\tbra.uni LW%=;\n\tLD%=:\n\t}"
        :: "r"(a), "r"(par) : "memory");
}
__device__ __forceinline__ void fence_async() {
    asm volatile("fence.proxy.async.shared::cta;" ::: "memory");
}
__device__ __forceinline__ void ldm_x4(uint32_t* r, uint32_t addr) {
    asm volatile("ldmatrix.sync.aligned.m8n8.x4.shared.b16 {%0,%1,%2,%3}, [%4];"
                 : "=r"(r[0]), "=r"(r[1]), "=r"(r[2]), "=r"(r[3]) : "r"(addr));
}
__device__ __forceinline__ void mma16816(float* d, const uint32_t* a, const uint32_t* b) {
    asm volatile(
        "mma.sync.aligned.m16n8k16.row.col.f32.bf16.bf16.f32 "
        "{%0,%1,%2,%3},{%4,%5,%6,%7},{%8,%9},{%0,%1,%2,%3};"
        : "+f"(d[0]), "+f"(d[1]), "+f"(d[2]), "+f"(d[3])
        : "r"(a[0]), "r"(a[1]), "r"(a[2]), "r"(a[3]), "r"(b[0]), "r"(b[1]));
}

__device__ __forceinline__ void tree_barrier(unsigned* bar, int bid, int tid,
                                             unsigned step1, unsigned perCtr) {
    if (tid == 0) atomicAdd(&bar[(bid & 7) * 32], 1u);
    if (tid < 8) {
        unsigned tgt = step1 * perCtr;
        while (*(volatile unsigned*)&bar[tid * 32] < tgt) {}
    }
    __syncthreads();
}

// ---- bf16 split stores ----
__device__ __forceinline__ void split_store_pair(unsigned char* st, int nCh, int blk,
                                                 int row, int kp, float v0, float v1) {
    int chunk = kp >> 6, kin = kp & 63;
    size_t base = ((size_t)(blk * nCh + chunk)) * PAIR_BYTES;
    unsigned so = swz((unsigned)(row * 128 + kin * 2));
    __nv_bfloat16 h0 = __float2bfloat16(v0), h1 = __float2bfloat16(v1);
    __nv_bfloat16 l0 = __float2bfloat16(v0 - __bfloat162float(h0));
    __nv_bfloat16 l1 = __float2bfloat16(v1 - __bfloat162float(h1));
    *(unsigned*)(st + base + so) =
        (unsigned)__bfloat16_as_ushort(h0) | ((unsigned)__bfloat16_as_ushort(h1) << 16);
    *(unsigned*)(st + base + TILE_BYTES + so) =
        (unsigned)__bfloat16_as_ushort(l0) | ((unsigned)__bfloat16_as_ushort(l1) << 16);
}
__device__ __forceinline__ void split_store_half(unsigned char* tileBase, int row, int kin,
                                                 float v) {
    unsigned so = swz((unsigned)(row * 128 + kin * 2));
    __nv_bfloat16 hi = __float2bfloat16(v);
    __nv_bfloat16 lo = __float2bfloat16(v - __bfloat162float(hi));
    *(unsigned short*)(tileBase + so) = __bfloat16_as_ushort(hi);
    *(unsigned short*)(tileBase + TILE_BYTES + so) = __bfloat16_as_ushort(lo);
}

// ---- prep ----
__device__ __forceinline__ void pack_region(const float* Wh, float* out, int H, long r) {
    long per = 4L * H * H;
    int dir = (int)(r / per);
    long s = r % per;
    int g = (int)(s & 3), jj = (int)((s >> 2) % H), k = (int)(s / (4 * H));
    out[dir * per + s] = Wh[dir * per + (size_t)(g * H + jj) * H + k];
}
#define R_SWH 524288L
#define R_DWS 2097152L
#define R_WB 2097152L
#define R_BW0 1179648L
#define R_BW1 2097152L
#define R_BQ 262144L
#define R_BDEC 3276800L
#define R_CEMB 131072L
#define R_PAD 131072L
#define R_BS0 327680L
#define R_BS1 524288L
#define R_EMBS 81920L
#define R_DLAB 262144L
#define R_CLS 15360L
#define PREP_BLOCKS 52860

__global__ void prep_kernel(const float* __restrict__ sWh0, const float* __restrict__ sWh1,
                            const float* __restrict__ wWh0, const float* __restrict__ wWh1,
                            const float* __restrict__ dWh, const float* __restrict__ wWx0,
                            const float* __restrict__ wWx1, const float* __restrict__ Wq,
                            const float* __restrict__ dWx, const int* __restrict__ words,
                            const float* __restrict__ char_table, const int* __restrict__ sents,
                            const float* __restrict__ word_embs, const int* __restrict__ labels,
                            const float* __restrict__ clsW, const float* __restrict__ sWx0,
                            const float* __restrict__ sWx1) {
    if (blockIdx.x == 0 && threadIdx.x < 8) {
        g_barT[threadIdx.x * 32] = 0u;
        g_barT2[threadIdx.x * 32] = 0u;
        g_barT3[threadIdx.x * 32] = 0u;
    }
    long idx = (long)blockIdx.x * 256 + threadIdx.x;
    if (idx < R_SWH) { pack_region(sWh0, g_sWh0P, SH_, idx); return; }
    idx -= R_SWH;
    if (idx < R_SWH) { pack_region(sWh1, g_sWh1P, SH_, idx); return; }
    idx -= R_SWH;
    if (idx < R_DWS) {
        int n = (int)(idx / 512), kp = 2 * (int)(idx % 512);
        split_store_pair(g_stDWr, 16, n >> 7, n & 127, kp,
                         dWh[(size_t)n * 1024 + kp], dWh[(size_t)n * 1024 + kp + 1]);
        return;
    }
    idx -= R_DWS;
    if (idx < R_WB) {
        int ld = (int)(idx >> 19);
        long e = idx & ((1L << 19) - 1);
        int r = (int)(e >> 8);
        int kp = 2 * (int)(e & 255);
        int g = r & 3, j = r >> 2;
        const float* Ws = (ld >> 1) ? wWh1 : wWh0;
        const float* w = Ws + (size_t)(ld & 1) * 4 * 512 * 512 + (size_t)(g * 512 + j) * 512;
        split_store_pair(g_stWw + (size_t)ld * 16 * 8 * PAIR_BYTES, 8, r >> 7, r & 127, kp,
                         w[kp], w[kp + 1]);
        return;
    }
    idx -= R_WB;
    if (idx < R_BW0) {
        int n = (int)(idx / 288), kp = 2 * (int)(idx % 288);
        float v0 = (kp < 544) ? wWx0[(size_t)n * 544 + kp] : 0.f;
        float v1 = (kp + 1 < 544) ? wWx0[(size_t)n * 544 + kp + 1] : 0.f;
        split_store_pair(g_stB_w0, NCH_W0, n >> 7, n & 127, kp, v0, v1);
        return;
    }
    idx -= R_BW0;
    if (idx < R_BW1) {
        int n = (int)(idx / 512), kp = 2 * (int)(idx % 512);
        split_store_pair(g_stB_w1, NCH_W1, n >> 7, n & 127, kp,
                         wWx1[(size_t)n * 1024 + kp], wWx1[(size_t)n * 1024 + kp + 1]);
        return;
    }
    idx -= R_BW1;
    if (idx < R_BQ) {
        int n = (int)(idx / 512), kp = 2 * (int)(idx % 512);
        split_store_pair(g_stB_q, NCH_Q, n >> 7, n & 127, kp,
                         Wq[(size_t)kp * 512 + n], Wq[(size_t)(kp + 1) * 512 + n]);
        return;
    }
    idx -= R_BQ;
    if (idx < R_BDEC) {
        int n = (int)(idx / 800), kp = 2 * (int)(idx % 800);
        float v0 = (kp < 1544) ? dWx[(size_t)n * 1544 + kp] : 0.f;
        float v1 = (kp + 1 < 1544) ? dWx[(size_t)n * 1544 + kp + 1] : 0.f;
        split_store_pair(g_stB_dec, NCH_DEC, n >> 7, n & 127, kp, v0, v1);
        return;
    }
    idx -= R_BDEC;
    if (idx < R_CEMB) {
        int r = (int)(idx / 16), kp = 2 * (int)(idx % 16);
        int w = words[r];
        split_store_pair(g_stageA, NCH_W0, r >> 7, r & 127, kp,
                         char_table[w * 32 + kp], char_table[w * 32 + kp + 1]);
        return;
    }
    idx -= R_CEMB;
    if (idx < R_PAD) {
        int r = (int)(idx / 16), kp = 544 + 2 * (int)(idx % 16);
        split_store_pair(g_stageA, NCH_W0, r >> 7, r & 127, kp, 0.f, 0.f);
        return;
    }
    idx -= R_PAD;
    if (idx < R_BS0) {
        int n = (int)(idx / 160), kp = 2 * (int)(idx % 160);
        int dir = n >> 10, j = n & 1023;
        const float* w = sWx0 + (size_t)dir * 1024 * 300 + (size_t)j * 300;
        float v0 = (kp < 300) ? w[kp] : 0.f;
        float v1 = (kp + 1 < 300) ? w[kp + 1] : 0.f;
        split_store_pair(g_stB_s0, 5, n >> 7, n & 127, kp, v0, v1);
        return;
    }
    idx -= R_BS0;
    if (idx < R_BS1) {
        int n = (int)(idx / 256), kp = 2 * (int)(idx % 256);
        int dir = n >> 10, j = n & 1023;
        const float* w = sWx1 + (size_t)dir * 1024 * 512 + (size_t)j * 512;
        split_store_pair(g_stB_s1, 8, n >> 7, n & 127, kp, w[kp], w[kp + 1]);
        return;
    }
    idx -= R_BS1;
    if (idx < R_EMBS) {
        int r = (int)(idx / 160), kp = 2 * (int)(idx % 160);
        const float* e = word_embs + (size_t)sents[r] * 300;
        float v0 = (kp < 300) ? e[kp] : 0.f;
        float v1 = (kp + 1 < 300) ? e[kp + 1] : 0.f;
        split_store_pair(g_stageS, 5, r >> 7, r & 127, kp, v0, v1);
        return;
    }
    idx -= R_EMBS;
    if (idx < R_DLAB) {
        int r = (int)(idx / 32), kp = 1536 + 2 * (int)(idx % 32);
        float v0 = (kp < 1544) ? (float)labels[r * 8 + (kp - 1536)] : 0.f;
        float v1 = (kp + 1 < 1544) ? (float)labels[r * 8 + (kp + 1 - 1536)] : 0.f;
        split_store_pair(g_stageD, NCH_DEC, r >> 7, r & 127, kp, v0, v1);
        return;
    }
    idx -= R_DLAB;
    if (idx < R_CLS) {
        int n = (int)(idx / 1024), k = (int)(idx % 1024);
        g_clsWT[n * 1024 + k] = clsW[(size_t)k * 15 + n];
    }
}

// ---- HMMA GEMM: 512 threads, 3-stage bulk-async pipeline ----
__global__ void __launch_bounds__(512) tgemm_kernel(
    const unsigned char* __restrict__ stA, const unsigned char* __restrict__ stB,
    const float* __restrict__ bias, float* __restrict__ C, int N, int nCh) {
    extern __shared__ unsigned char smraw[];
    uint32_t smb = smem_u32(smraw);
    uint32_t ab = (smb + 1023) & ~1023u;
    uint32_t ctrl = ab + 196608;
    int tid = threadIdx.x, lane = tid & 31, wid = tid >> 5;
    int wm = wid & 3, wn = wid >> 2;
    int nb = blockIdx.x, mb = blockIdx.y;

    if (tid == 0) {
        mbar_init(ctrl, 1);
        mbar_init(ctrl + 8, 1);
        mbar_init(ctrl + 16, 1);
        fence_async();
    }
    __syncthreads();

    float acc[2][4][4];
#pragma unroll
    for (int i = 0; i < 2; ++i)
#pragma unroll
        for (int j = 0; j < 4; ++j)
#pragma unroll
            for (int k = 0; k < 4; ++k) acc[i][j][k] = 0.f;

    int ar = (lane & 7) + ((lane >> 3) & 1) * 8;
    int ac = (lane >> 4) * 16;
    int br = (lane & 7) + ((lane >> 4) & 1) * 8;
    int bc = ((lane >> 3) & 1) * 16;

    auto issue = [&](int c) {
        if (tid == 0) {
            int buf = c % 3;
            uint32_t bar = ctrl + buf * 8;
            uint32_t dst = ab + buf * 65536;
            mbar_expect_tx(bar, 65536u);
            cp_bulk(dst, stA + ((size_t)mb * nCh + c) * PAIR_BYTES, 32768u, bar);
            cp_bulk(dst + 32768, stB + ((size_t)nb * nCh + c) * PAIR_BYTES, 32768u, bar);
        }
    };

    issue(0);
    if (nCh > 1) issue(1);
    if (nCh > 2) issue(2);
    for (int c = 0; c < nCh; ++c) {
        int buf = c % 3;
        mbar_wait(ctrl + buf * 8, (c / 3) & 1);
        uint32_t base = ab + buf * 65536;
#pragma unroll
        for (int ks = 0; ks < 4; ++ks) {
            uint32_t ah[2][4], al[2][4], bh[2][4], bl[2][4];
#pragma unroll
            for (int mf = 0; mf < 2; ++mf) {
                uint32_t off = swz((unsigned)((wm * 32 + mf * 16 + ar) * 128 + ac + ks * 32));
                ldm_x4(ah[mf], base + off);
                ldm_x4(al[mf], base + 16384 + off);
            }
#pragma unroll
            for (int nf2 = 0; nf2 < 2; ++nf2) {
                uint32_t off = swz((unsigned)((wn * 32 + nf2 * 16 + br) * 128 + bc + ks * 32));
                ldm_x4(bh[nf2], base + 32768 + off);
                ldm_x4(bl[nf2], base + 49152 + off);
            }
#pragma unroll
            for (int mf = 0; mf < 2; ++mf)
#pragma unroll
                for (int nf = 0; nf < 4; ++nf) {
                    mma16816(acc[mf][nf], ah[mf], &bh[nf >> 1][(nf & 1) * 2]);
                    mma16816(acc[mf][nf], ah[mf], &bl[nf >> 1][(nf & 1) * 2]);
                    mma16816(acc[mf][nf], al[mf], &bh[nf >> 1][(nf & 1) * 2]);
                }
        }
        __syncthreads();
        if (c + 3 < nCh) issue(c + 3);
    }
#pragma unroll
    for (int mf = 0; mf < 2; ++mf) {
#pragma unroll
        for (int nf = 0; nf < 4; ++nf) {
            int row = mb * 128 + wm * 32 + mf * 16 + (lane >> 2);
            int col = nb * 128 + wn * 32 + nf * 8 + (lane & 3) * 2;
            float b0 = bias ? bias[col] : 0.f;
            float b1 = bias ? bias[col + 1] : 0.f;
            float2 v0 = make_float2(acc[mf][nf][0] + b0, acc[mf][nf][1] + b1);
            float2 v1 = make_float2(acc[mf][nf][2] + b0, acc[mf][nf][3] + b1);
            *(float2*)(C + (size_t)row * N + col) = v0;
            *(float2*)(C + (size_t)(row + 8) * N + col) = v1;
        }
    }
}

// ---- persistent HMMA word-LSTM recurrence (bulk-async chunk staging) ----
__global__ void __launch_bounds__(256) wordrec_kernel(
    const unsigned char* __restrict__ stW, const float* __restrict__ pre,
    int writeDec, int base) {
    extern __shared__ unsigned char dsm[];
    uint32_t smb = smem_u32(dsm);
    uint32_t wctrl = smb + 131072 + 98304;
    int tid = threadIdx.x, lane = tid & 31, wid = tid >> 5;
    int wm = wid & 1, wn = wid >> 1;
    int bid = blockIdx.x;
    int dir = bid >> 6, r6 = bid & 63, mb = r6 >> 4, nt = r6 & 15;

    if (tid == 0) {
        mbar_init(wctrl, 1);
        mbar_init(wctrl + 8, 1);
        fence_async();
    }
    {
        const unsigned char* wb = stW + ((size_t)(dir * 16 + nt)) * 8 * PAIR_BYTES;
        uint4* dst = (uint4*)dsm;
#pragma unroll 4
        for (int i = tid; i < 8192; i += 256) {
            int c = i >> 10, w = i & 1023;
            dst[i] = *(const uint4*)(wb + (size_t)c * PAIR_BYTES + w * 16);
        }
    }
    __syncthreads();

    int ar = (lane & 7) + ((lane >> 3) & 1) * 8;
    int ac = (lane >> 4) * 16;
    int br = (lane & 7) + ((lane >> 4) & 1) * 8;
    int bc = ((lane >> 3) & 1) * 16;

    float cacc[4][4][2];
#pragma unroll
    for (int a = 0; a < 4; ++a)
#pragma unroll
        for (int b = 0; b < 4; ++b) { cacc[a][b][0] = 0.f; cacc[a][b][1] = 0.f; }

    int ph0 = 0, ph1 = 0;

    for (int t = 0; t < 16; ++t) {
        int rb = t & 1, wbuf = rb ^ 1;
        int tdir = dir ? (15 - t) : t;

        auto issueW = [&](int c) {
            if (tid == 0) {
                int buf = c & 1;
                uint32_t bar = wctrl + buf * 8;
                uint32_t dst = smb + 131072 + buf * 49152;
                mbar_expect_tx(bar, 49152u);
                cp_bulk(dst,
                        g_hstage + (((size_t)((dir * 2 + rb) * 4 + mb)) * 8 + c) * PAIR_BYTES,
                        32768u, bar);
                cp_bulk(dst + 32768,
                        stW + (((size_t)(dir * 16 + nt)) * 8 + c) * PAIR_BYTES + TILE_BYTES,
                        16384u, bar);
            }
        };

        float acc[4][4][4];
#pragma unroll
        for (int a = 0; a < 4; ++a)
#pragma unroll
            for (int b = 0; b < 4; ++b)
#pragma unroll
                for (int k = 0; k < 4; ++k) acc[a][b][k] = 0.f;

        if (t > 0) {
            issueW(0);
            issueW(1);
            for (int c = 0; c < 8; ++c) {
                int buf = c & 1;
                mbar_wait(wctrl + buf * 8, buf ? ph1 : ph0);
                if (buf) ph1 ^= 1; else ph0 ^= 1;
                uint32_t sb = smb + 131072 + buf * 49152;
                uint32_t bhb = smb + c * 16384;
#pragma unroll
                for (int ks = 0; ks < 4; ++ks) {
                    uint32_t ah[4][4], al[4][4], bh[2][4], bl[2][4];
#pragma unroll
                    for (int mf = 0; mf < 4; ++mf) {
                        uint32_t off = swz((unsigned)((wm * 64 + mf * 16 + ar) * 128 + ac + ks * 32));
                        ldm_x4(ah[mf], sb + off);
                        ldm_x4(al[mf], sb + 16384 + off);
                    }
#pragma unroll
                    for (int nf2 = 0; nf2 < 2; ++nf2) {
                        uint32_t off = swz((unsigned)((wn * 32 + nf2 * 16 + br) * 128 + bc + ks * 32));
                        ldm_x4(bh[nf2], bhb + off);
                        ldm_x4(bl[nf2], sb + 32768 + off);
                    }
#pragma unroll
                    for (int mf = 0; mf < 4; ++mf)
#pragma unroll
                        for (int nf = 0; nf < 4; ++nf) {
                            mma16816(acc[mf][nf], ah[mf], &bh[nf >> 1][(nf & 1) * 2]);
                            mma16816(acc[mf][nf], ah[mf], &bl[nf >> 1][(nf & 1) * 2]);
                            mma16816(acc[mf][nf], al[mf], &bh[nf >> 1][(nf & 1) * 2]);
                        }
                }
                __syncthreads();
                if (c + 2 < 8) issueW(c + 2);
            }
        }

#pragma unroll
        for (int mf = 0; mf < 4; ++mf)
#pragma unroll
            for (int nf = 0; nf < 4; ++nf) {
                float p0 = __shfl_xor_sync(0xffffffffu, acc[mf][nf][0], 1);
                float p1 = __shfl_xor_sync(0xffffffffu, acc[mf][nf][1], 1);
                float p2 = __shfl_xor_sync(0xffffffffu, acc[mf][nf][2], 1);
                float p3 = __shfl_xor_sync(0xffffffffu, acc[mf][nf][3], 1);
                if (!(lane & 1)) {
                    int j = nt * 32 + wn * 8 + nf * 2 + ((lane & 3) >> 1);
                    int r0 = wm * 64 + mf * 16 + (lane >> 2);
#pragma unroll
                    for (int rr = 0; rr < 2; ++rr) {
                        int r = r0 + rr * 8;
                        int n = mb * 128 + r;
                        size_t pb = (size_t)(n * 16 + tdir) * 4096 + dir * 2048 + j;
                        float ai = (rr ? acc[mf][nf][2] : acc[mf][nf][0]) + pre[pb];
                        float af = (rr ? acc[mf][nf][3] : acc[mf][nf][1]) + pre[pb + 512];
                        float ag = (rr ? p2 : p0) + pre[pb + 1024];
                        float ao = (rr ? p3 : p1) + pre[pb + 1536];
                        float cv = cacc[mf][nf][rr];
                        cv = sigm(af) * cv + sigm(ai) * tanhf(ag);
                        float hn = sigm(ao) * tanhf(cv);
                        cacc[mf][nf][rr] = cv;
                        split_store_half(
                            g_hstage + (((size_t)((dir * 2 + wbuf) * 4 + mb)) * 8 + (j >> 6)) * PAIR_BYTES,
                            r, j & 63, hn);
                        int rA = n * 16 + tdir, kp = dir * 512 + j;
                        split_store_half(
                            g_stageA + (((size_t)(rA >> 7) * 16 + (kp >> 6))) * PAIR_BYTES,
                            rA & 127, kp & 63, hn);
                        if (writeDec) {
                            int kp2 = 512 + kp;
                            split_store_half(
                                g_stageD + (((size_t)(rA >> 7) * 25 + (kp2 >> 6))) * PAIR_BYTES,
                                rA & 127, kp2 & 63, hn);
                        }
                    }
                }
            }
        __threadfence();
        __syncthreads();
        tree_barrier(g_barT2, bid, tid, (unsigned)(base + t + 1), 16u);
    }
}

// ---- persistent HMMA decoder ----
__global__ void __launch_bounds__(256) dec_persist_kernel(
    const float* __restrict__ pre, float* __restrict__ dout) {
    extern __shared__ unsigned char dsm[];
    uint32_t smb = smem_u32(dsm);
    int tid = threadIdx.x, lane = tid & 31, w = tid >> 5;
    int bid = blockIdx.x;
    {
        const uint4* src = (const uint4*)g_stDWr;
        uint4* dst = (uint4*)dsm;
#pragma unroll 4
        for (int it = 0; it < 32; ++it) {
            int flat = tid + it * 256;
            int q = flat & 7;
            int ru = flat >> 3;
            int i = ru & 7;
            int hl = (ru >> 3) & 1;
            int g = (ru >> 4) & 3;
            int c = ru >> 6;
            size_t sb = ((((size_t)(g * 8 + (bid >> 4)) * 16 + c) * PAIR_BYTES
                         + (size_t)hl * TILE_BYTES
                         + (size_t)((bid & 15) * 8 + i) * 128) >> 4) + q;
            int db = ((c * 8192 + hl * 4096 + (g * 8 + i) * 128) >> 4) + q;
            dst[db] = src[sb];
        }
    }
    __syncthreads();

    float* red = (float*)(dsm + 131072);
    const unsigned* hHr[2] = {(const unsigned*)&g_hsplitH[0][0], (const unsigned*)&g_hsplitH[1][0]};
    const unsigned* hLr[2] = {(const unsigned*)&g_hsplitL[0][0], (const unsigned*)&g_hsplitL[1][0]};

    int bb = tid >> 3, hh = tid & 7;
    int j = bid * 8 + hh;
    float cc = 0.f;

    int br = (lane & 7) + ((lane >> 4) & 1) * 8;
    int bc = ((lane >> 3) & 1) * 16;
    int k0base = w * 128;

    for (int t = 0; t < 256; ++t) {
        int rb = t & 1;
        const float* p = pre + ((size_t)bb * 256 + t) * 4096 + j;
        float px0 = p[0], px1 = p[1024], px2 = p[2048], px3 = p[3072];

        float acc[2][4][4];
#pragma unroll
        for (int m = 0; m < 2; ++m)
#pragma unroll
            for (int g = 0; g < 4; ++g)
#pragma unroll
                for (int r4 = 0; r4 < 4; ++r4) acc[m][g][r4] = 0.f;

        if (t > 0) {
#pragma unroll 2
            for (int kf = 0; kf < 8; ++kf) {
                int k0 = k0base + kf * 16;
                uint32_t ah[2][4], al[2][4];
#pragma unroll
                for (int m = 0; m < 2; ++m) {
                    int base2 = ((m * 16 + (lane >> 2)) * 1024 + k0) / 2 + (lane & 3);
                    ah[m][0] = __ldcg(hHr[rb] + base2);
                    ah[m][1] = __ldcg(hHr[rb] + base2 + 4096);
                    ah[m][2] = __ldcg(hHr[rb] + base2 + 4);
                    ah[m][3] = __ldcg(hHr[rb] + base2 + 4100);
                    al[m][0] = __ldcg(hLr[rb] + base2);
                    al[m][1] = __ldcg(hLr[rb] + base2 + 4096);
                    al[m][2] = __ldcg(hLr[rb] + base2 + 4);
                    al[m][3] = __ldcg(hLr[rb] + base2 + 4100);
                }
                int chunk = k0 >> 6, kin = k0 & 63;
                uint32_t cbs = smb + chunk * 8192;
                uint32_t bh[2][4], bl[2][4];
#pragma unroll
                for (int nt = 0; nt < 2; ++nt) {
                    uint32_t off = swz((unsigned)((nt * 16 + br) * 128 + bc + kin * 2));
                    ldm_x4(bh[nt], cbs + off);
                    ldm_x4(bl[nt], cbs + 4096 + off);
                }
#pragma unroll
                for (int m = 0; m < 2; ++m)
#pragma unroll
                    for (int g = 0; g < 4; ++g) {
                        mma16816(acc[m][g], ah[m], &bh[g >> 1][(g & 1) * 2]);
                        mma16816(acc[m][g], ah[m], &bl[g >> 1][(g & 1) * 2]);
                        mma16816(acc[m][g], al[m], &bh[g >> 1][(g & 1) * 2]);
                    }
            }
        }
#pragma unroll
        for (int m = 0; m < 2; ++m)
#pragma unroll
            for (int g = 0; g < 4; ++g)
#pragma unroll
                for (int r4 = 0; r4 < 4; ++r4)
                    red[((w * 2 + m) * 4 + g) * 128 + lane * 4 + r4] = acc[m][g][r4];
        __syncthreads();
        {
            int r = bb & 15, m = bb >> 4;
            int gl = ((r & 7) << 2) | (hh >> 1);
            int rg = (hh & 1) + 2 * ((r >> 3) & 1);
            float gv[4] = {0.f, 0.f, 0.f, 0.f};
#pragma unroll
            for (int w2 = 0; w2 < 8; ++w2)
#pragma unroll
                for (int g = 0; g < 4; ++g)
                    gv[g] += red[((w2 * 2 + m) * 4 + g) * 128 + gl * 4 + rg];
            float ai = gv[0] + px0;
            float af = gv[1] + px1;
            float agg = gv[2] + px2;
            float ao = gv[3] + px3;
            cc = sigm(af) * cc + sigm(ai) * tanhf(agg);
            float hn = sigm(ao) * tanhf(cc);
            dout[((size_t)bb * 256 + t) * 1024 + j] = hn;
            __nv_bfloat16 hi = __float2bfloat16(hn);
            __nv_bfloat16 lo = __float2bfloat16(hn - __bfloat162float(hi));
            g_hsplitH[rb ^ 1][bb * 1024 + j] = hi;
            g_hsplitL[rb ^ 1][bb * 1024 + j] = lo;
        }
        __threadfence();
        __syncthreads();
        tree_barrier(g_barT, bid, tid, (unsigned)(t + 1), 16u);
    }
}

// ---- persistent sentence BiLSTM recurrence ----
template <int MODE>
__global__ void __launch_bounds__(256) sentrec_kernel(
    const float* __restrict__ pre, const float* __restrict__ WhP,
    float* __restrict__ out, const int* __restrict__ words, int base) {
    extern __shared__ unsigned char sms[];
    float4* wS = (float4*)sms;
    float* hsm = (float*)(sms + 65536);
    float* wm = (float*)(sms + 65536 + 16384);
    int tid = threadIdx.x, bid = blockIdx.x;
    int dir = bid >> 5, jb = (bid >> 1) & 15, sb = bid & 1;
    int jl = tid & 15, sq = tid >> 4;
    int s = sb * 16 + sq;
    int j = jb * 16 + jl;

    const float4* Wsrc = (const float4*)(WhP + (size_t)dir * (256 * 256 * 4));
    for (int i = tid; i < 4096; i += 256) {
        int k = i >> 4;
        wS[i] = Wsrc[k * 256 + jb * 16 + (i & 15)];
    }
    if (MODE == 1) {
        for (int x = tid; x < 4096; x += 256)
            wm[x] = (words[(sb * 16 + (x >> 8)) * 256 + (x & 255)] != 0) ? 1.f : 0.f;
    }
    float cc = 0.f;
    __syncthreads();

    for (int tt = 0; tt < 16; ++tt) {
        int rb = tt & 1;
        int t = dir ? (15 - tt) : tt;
        if (tt > 0) {
            const float4* src = (const float4*)(g_shs + ((rb * 2 + dir) * 32 + sb * 16) * 256);
            float4* dst = (float4*)hsm;
#pragma unroll
            for (int i = 0; i < 4; ++i) dst[tid + i * 256] = __ldcg(src + tid + i * 256);
            __syncthreads();
        }
        size_t pb = ((size_t)(s * 16 + t) * 2 + dir) * 1024 + j;
        float ai = pre[pb], af = pre[pb + 256], ag = pre[pb + 512], ao = pre[pb + 768];
        if (tt > 0) {
#pragma unroll 8
            for (int k = 0; k < 256; ++k) {
                float4 w = wS[k * 16 + jl];
                float hk = hsm[sq * 256 + k];
                ai += hk * w.x; af += hk * w.y; ag += hk * w.z; ao += hk * w.w;
            }
        }
        float cv = sigm(af) * cc + sigm(ai) * tanhf(ag);
        float hn = sigm(ao) * tanhf(cv);
        cc = cv;
        g_shs[(((rb ^ 1) * 2 + dir) * 32 + s) * 256 + j] = hn;
        if (MODE == 0) {
            int r = s * 16 + t, kp = dir * 256 + j;
            split_store_half(g_stageS2 + ((size_t)((r >> 7) * 8 + (kp >> 6))) * PAIR_BYTES,
                             r & 127, kp & 63, hn);
        } else {
            out[((size_t)s * 16 + t) * 512 + dir * 256 + j] = hn;
            float v1 = __shfl_down_sync(0xffffffffu, hn, 1);
            if (!(jl & 1)) {
                int kp = 32 + dir * 256 + j;
                int rbrow = (s * 16 + t) * 16;
                int blk = rbrow >> 7;
#pragma unroll
                for (int tw = 0; tw < 16; ++tw) {
                    float m = wm[sq * 256 + t * 16 + tw];
                    split_store_pair(g_stageA, NCH_W0, blk, (rbrow & 127) + tw, kp, hn * m, v1 * m);
                }
            }
        }
        __threadfence();
        __syncthreads();
        tree_barrier(g_barT3, bid, tid, (unsigned)(base + tt + 1), 8u);
    }
}

// ---- attention ----
__global__ void attention_kernel(const float* __restrict__ q, const float* __restrict__ sent_enc,
                                 const int* __restrict__ words, float* __restrict__ map_out) {
    int bi = blockIdx.x, b = bi >> 4, i = bi & 15;
    __shared__ float se[16 * 513];
    __shared__ float sc[16][16];
    __shared__ float mp[16][16];
    __shared__ int kv[16];
    for (int x = threadIdx.x; x < 16 * 512; x += 256) {
        int jj = x >> 9, d = x & 511;
        se[jj * 513 + d] = sent_enc[((size_t)b * 16 + jj) * 512 + d];
    }
    if (threadIdx.x < 16) {
        int jj = threadIdx.x, any = 0;
        for (int tw = 0; tw < 16; ++tw) any |= (words[(b * 16 + jj) * 16 + tw] != 0);
        kv[jj] = any;
    }
    __syncthreads();
    {
        int cdx = threadIdx.x >> 4, jj = threadIdx.x & 15;
        const float* qr = q + ((size_t)bi * 16 + cdx) * 512;
        const float* ser = se + jj * 513;
        float s = 0.f;
#pragma unroll 4
        for (int d = 0; d < 512; ++d) s += qr[d] * ser[d];
        sc[cdx][jj] = s;
    }
    __syncthreads();
    if (threadIdx.x < 16) {
        int cdx = threadIdx.x;
        float v[16], m = -1e30f;
#pragma unroll
        for (int jj = 0; jj < 16; ++jj) {
            bool valid = (kv[jj] != 0) && (jj != i);
            v[jj] = valid ? sc[cdx][jj] : -1e9f;
            m = fmaxf(m, v[jj]);
        }
        float sum = 0.f;
#pragma unroll
        for (int jj = 0; jj < 16; ++jj) { v[jj] = expf(v[jj] - m); sum += v[jj]; }
        float inv = 1.f / sum;
#pragma unroll
        for (int jj = 0; jj < 16; ++jj) mp[cdx][jj] = v[jj] * inv;
    }
    __syncthreads();
    if (map_out != nullptr && threadIdx.x < 256) {
        int x = threadIdx.x;
        map_out[(size_t)bi * 256 + x] = mp[x >> 4][x & 15];
    }
    for (int x = threadIdx.x; x < 16 * 512; x += 256) {
        int cdx = x >> 9, d = x & 511;
        float s = 0.f;
#pragma unroll
        for (int jj = 0; jj < 16; ++jj) s += mp[cdx][jj] * se[jj * 513 + d];
        int r = bi * 16 + cdx;
        split_store_half(g_stageD + ((size_t)(r >> 7) * 25 + (d >> 6)) * PAIR_BYTES,
                         r & 127, d & 63, s);
    }
}

// ---- classifier: warp per row ----
__global__ void __launch_bounds__(256) classifier_kernel(
    const float* __restrict__ dec_out, const float* __restrict__ Wt,
    const float* __restrict__ bias, float* __restrict__ out) {
    __shared__ float res[8][16];
    int w = threadIdx.x >> 5, lane = threadIdx.x & 31;
    int m = blockIdx.x * 8 + w;
    const float4* x4 = (const float4*)(dec_out + (size_t)m * 1024);
    float4 xv[8];
#pragma unroll
    for (int i = 0; i < 8; ++i) xv[i] = x4[lane + i * 32];
#pragma unroll
    for (int n = 0; n < 15; ++n) {
        const float4* w4 = (const float4*)(Wt + n * 1024);
        float s = 0.f;
#pragma unroll
        for (int i = 0; i < 8; ++i) {
            float4 b = w4[lane + i * 32];
            s += xv[i].x * b.x + xv[i].y * b.y + xv[i].z * b.z + xv[i].w * b.w;
        }
#pragma unroll
        for (int o = 16; o; o >>= 1) s += __shfl_xor_sync(0xffffffffu, s, o);
        if (lane == 0) res[w][n] = s + bias[n];
    }
    __syncthreads();
    for (int i = threadIdx.x; i < 120; i += 256) {
        int mr = i / 15, n = i % 15;
        out[(size_t)(blockIdx.x * 8 + mr) * 15 + n] = res[mr][n];
    }
}

// ---- host ----
static void* symp(const void* s) { void* p = nullptr; cudaGetSymbolAddress(&p, s); return p; }

extern "C" void kernel_launch(void* const* d_in, const int* in_sizes, int n_in,
                              void* d_out, int out_size) {
    (void)in_sizes; (void)n_in;
    const int* sents = (const int*)d_in[0];
    const int* words = (const int*)d_in[1];
    const int* labels = (const int*)d_in[2];
    const float* word_embs = (const float*)d_in[3];
    const float* char_table = (const float*)d_in[4];
    const float* sWx0 = (const float*)d_in[5];
    const float* sWh0 = (const float*)d_in[6];
    const float* sb0 = (const float*)d_in[7];
    const float* sWx1 = (const float*)d_in[8];
    const float* sWh1 = (const float*)d_in[9];
    const float* sb1 = (const float*)d_in[10];
    const float* wWx0 = (const float*)d_in[11];
    const float* wWh0 = (const float*)d_in[12];
    const float* wb0 = (const float*)d_in[13];
    const float* wWx1 = (const float*)d_in[14];
    const float* wWh1 = (const float*)d_in[15];
    const float* wb1 = (const float*)d_in[16];
    const float* Wq = (const float*)d_in[17];
    const float* dWx = (const float*)d_in[18];
    const float* dWh = (const float*)d_in[19];
    const float* db = (const float*)d_in[20];
    const float* clsW = (const float*)d_in[21];
    const float* clsb = (const float*)d_in[22];
    float* out = (float*)d_out;

    float* pre_s = (float*)symp(g_pre_s);
    float* sent_enc = (float*)symp(g_sent_enc);
    float* pre_w = (float*)symp(g_pre_w);
    float* qbuf = (float*)symp(g_q);
    float* pre_d = (float*)symp(g_pre_d);
    float* dec_out = (float*)symp(g_dec_out);
    float* sWh0P = (float*)symp(g_sWh0P);
    float* sWh1P = (float*)symp(g_sWh1P);
    float* clsWT = (float*)symp(g_clsWT);
    const unsigned char* stA = (const unsigned char*)symp(g_stageA);
    const unsigned char* stD = (const unsigned char*)symp(g_stageD);
    const unsigned char* stS = (const unsigned char*)symp(g_stageS);
    const unsigned char* stS2 = (const unsigned char*)symp(g_stageS2);
    const unsigned char* stBs0 = (const unsigned char*)symp(g_stB_s0);
    const unsigned char* stBs1 = (const unsigned char*)symp(g_stB_s1);
    const unsigned char* stBw0 = (const unsigned char*)symp(g_stB_w0);
    const unsigned char* stBw1 = (const unsigned char*)symp(g_stB_w1);
    const unsigned char* stBq = (const unsigned char*)symp(g_stB_q);
    const unsigned char* stBdec = (const unsigned char*)symp(g_stB_dec);
    const unsigned char* stWw = (const unsigned char*)symp(g_stWw);

    cudaFuncSetAttribute(tgemm_kernel, cudaFuncAttributeMaxDynamicSharedMemorySize, TG_SMEM);
    cudaFuncSetAttribute(dec_persist_kernel, cudaFuncAttributeMaxDynamicSharedMemorySize, DEC_SMEM);
    cudaFuncSetAttribute(wordrec_kernel, cudaFuncAttributeMaxDynamicSharedMemorySize, WR_SMEM);
    cudaFuncSetAttribute(sentrec_kernel<0>, cudaFuncAttributeMaxDynamicSharedMemorySize, SR_SMEM);
    cudaFuncSetAttribute(sentrec_kernel<1>, cudaFuncAttributeMaxDynamicSharedMemorySize, SR_SMEM);

    const size_t wwLayer = 2ul * 16 * 8 * PAIR_BYTES;

    prep_kernel<<<PREP_BLOCKS, 256>>>(sWh0, sWh1, wWh0, wWh1, dWh, wWx0, wWx1, Wq, dWx,
                                      words, char_table, sents, word_embs, labels, clsW,
                                      sWx0, sWx1);
    tgemm_kernel<<<dim3(16, 4), 512, TG_SMEM>>>(stS, stBs0, sb0, pre_s, 2048, 5);
    sentrec_kernel<0><<<64, 256, SR_SMEM>>>(pre_s, sWh0P, nullptr, nullptr, 0);
    tgemm_kernel<<<dim3(16, 4), 512, TG_SMEM>>>(stS2, stBs1, sb1, pre_s, 2048, 8);
    sentrec_kernel<1><<<64, 256, SR_SMEM>>>(pre_s, sWh1P, sent_enc, words, 16);
    tgemm_kernel<<<dim3(32, 64), 512, TG_SMEM>>>(stA, stBw0, wb0, pre_w, 4096, NCH_W0);
    wordrec_kernel<<<128, 256, WR_SMEM>>>(stWw, pre_w, 0, 0);
    tgemm_kernel<<<dim3(32, 64), 512, TG_SMEM>>>(stA, stBw1, wb1, pre_w, 4096, NCH_W1);
    wordrec_kernel<<<128, 256, WR_SMEM>>>(stWw + wwLayer, pre_w, 1, 16);
    tgemm_kernel<<<dim3(4, 64), 512, TG_SMEM>>>(stA, stBq, nullptr, qbuf, 512, NCH_Q);
    float* map_out = (out_size >= (NR_ * 15 + 131072)) ? (out + NR_ * 15) : nullptr;
    attention_kernel<<<NSEQ_, 256>>>(qbuf, sent_enc, words, map_out);
    tgemm_kernel<<<dim3(32, 64), 512, TG_SMEM>>>(stD, stBdec, db, pre_d, 4096, NCH_DEC);
    dec_persist_kernel<<<128, 256, DEC_SMEM>>>(pre_d, dec_out);
    classifier_kernel<<<NR_ / 8, 256>>>(dec_out, clsWT, clsb, out);
}

// round 15
// speedup vs baseline: 1.2190x; 1.2175x over previous
#include <cuda_runtime.h>
#include <cuda_bf16.h>
#include <cuda_fp16.h>
#include <math.h>
#include <stdint.h>

#define B_ 32
#define SH_ 256
#define WH_ 512
#define DH_ 1024
#define NSEQ_ 512
#define NR_ 8192
#define NCH_W0 9
#define NCH_W1 16
#define NCH_Q 16
#define NCH_DEC 25
#define TILE_BYTES 16384
#define PAIR_BYTES 32768
#define TG_SMEM (3 * 32768 + 1088)
#define DEC_SMEM (131072 + 32768)
#define WR_SMEM (131072 + 2 * 49152 + 64)
#define SR_SMEM (65536 + 16384 + 16384)

#define DEVBUF __device__ __align__(16)
DEVBUF float g_pre_s[NSEQ_ * 2048];
DEVBUF float g_sent_enc[NSEQ_ * 512];
DEVBUF float g_pre_w[NR_ * 4096];
DEVBUF float g_q[NR_ * 512];
DEVBUF float g_pre_d[NR_ * 4096];
DEVBUF float g_dec_out[NR_ * 1024];
DEVBUF float g_sWh0P[2 * SH_ * SH_ * 4];
DEVBUF float g_sWh1P[2 * SH_ * SH_ * 4];
DEVBUF float g_clsWT[15 * 1024];
DEVBUF float g_shs[2 * 2 * 32 * 256];
// fp16 single-pass staging for feed-forward GEMMs
DEVBUF unsigned char g_stageA[64ul * 16 * TILE_BYTES];
DEVBUF unsigned char g_stageD[64ul * 25 * TILE_BYTES];
DEVBUF unsigned char g_stageS[4ul * 5 * TILE_BYTES];
DEVBUF unsigned char g_stageS2[4ul * 8 * TILE_BYTES];
DEVBUF unsigned char g_stB_s0[16ul * 5 * TILE_BYTES];
DEVBUF unsigned char g_stB_s1[16ul * 8 * TILE_BYTES];
DEVBUF unsigned char g_stB_w0[32ul * NCH_W0 * TILE_BYTES];
DEVBUF unsigned char g_stB_w1[32ul * NCH_W1 * TILE_BYTES];
DEVBUF unsigned char g_stB_q[4ul * NCH_Q * TILE_BYTES];
DEVBUF unsigned char g_stB_dec[32ul * NCH_DEC * TILE_BYTES];
// split-bf16 recurrence weights/state (unchanged from R14)
DEVBUF unsigned char g_stDWr[32ul * 16 * PAIR_BYTES];
DEVBUF unsigned char g_stWw[4ul * 16 * 8 * PAIR_BYTES];
DEVBUF unsigned char g_hstage[128ul * PAIR_BYTES];
DEVBUF __nv_bfloat16 g_hsplitH[2][B_ * DH_];
DEVBUF __nv_bfloat16 g_hsplitL[2][B_ * DH_];
DEVBUF unsigned g_barT[8 * 32];
DEVBUF unsigned g_barT2[8 * 32];
DEVBUF unsigned g_barT3[8 * 32];

__device__ __forceinline__ float sigm(float x) { return 1.f / (1.f + expf(-x)); }
__device__ __forceinline__ unsigned swz(unsigned o) { return o ^ ((o >> 3) & 0x70); }

__device__ __forceinline__ uint32_t smem_u32(const void* p) {
    uint32_t a;
    asm("{ .reg .u64 t; cvta.to.shared.u64 t, %1; cvt.u32.u64 %0, t; }" : "=r"(a) : "l"(p));
    return a;
}
__device__ __forceinline__ void cp_bulk(uint32_t dst, const void* src, uint32_t bytes,
                                        uint32_t mbar) {
    asm volatile(
        "cp.async.bulk.shared::cta.global.mbarrier::complete_tx::bytes [%0], [%1], %2, [%3];"
        :: "r"(dst), "l"(src), "r"(bytes), "r"(mbar) : "memory");
}
__device__ __forceinline__ void mbar_init(uint32_t a, uint32_t c) {
    asm volatile("mbarrier.init.shared.b64 [%0], %1;" :: "r"(a), "r"(c) : "memory");
}
__device__ __forceinline__ void mbar_expect_tx(uint32_t a, uint32_t bytes) {
    asm volatile("mbarrier.arrive.expect_tx.shared.b64 _, [%0], %1;"
                 :: "r"(a), "r"(bytes) : "memory");
}
__device__ __forceinline__ void mbar_wait(uint32_t a, uint32_t par) {
    asm volatile(
        "{\n\t.reg .pred P1;\n\tLW%=:\n\t"
        "mbarrier.try_wait.parity.acquire.cta.shared::cta.b64 P1, [%0], %1, 0x989680;\n\t"
        "@P1 bra.uni LD%=;\n\tbra.uni LW%=;\n\tLD%=:\n\t}"
        :: "r"(a), "r"(par) : "memory");
}
__device__ __forceinline__ void fence_async() {
    asm volatile("fence.proxy.async.shared::cta;" ::: "memory");
}
__device__ __forceinline__ void ldm_x4(uint32_t* r, uint32_t addr) {
    asm volatile("ldmatrix.sync.aligned.m8n8.x4.shared.b16 {%0,%1,%2,%3}, [%4];"
                 : "=r"(r[0]), "=r"(r[1]), "=r"(r[2]), "=r"(r[3]) : "r"(addr));
}
__device__ __forceinline__ void mma16816(float* d, const uint32_t* a, const uint32_t* b) {
    asm volatile(
        "mma.sync.aligned.m16n8k16.row.col.f32.bf16.bf16.f32 "
        "{%0,%1,%2,%3},{%4,%5,%6,%7},{%8,%9},{%0,%1,%2,%3};"
        : "+f"(d[0]), "+f"(d[1]), "+f"(d[2]), "+f"(d[3])
        : "r"(a[0]), "r"(a[1]), "r"(a[2]), "r"(a[3]), "r"(b[0]), "r"(b[1]));
}
__device__ __forceinline__ void mmah16816(float* d, const uint32_t* a, const uint32_t* b) {
    asm volatile(
        "mma.sync.aligned.m16n8k16.row.col.f32.f16.f16.f32 "
        "{%0,%1,%2,%3},{%4,%5,%6,%7},{%8,%9},{%0,%1,%2,%3};"
        : "+f"(d[0]), "+f"(d[1]), "+f"(d[2]), "+f"(d[3])
        : "r"(a[0]), "r"(a[1]), "r"(a[2]), "r"(a[3]), "r"(b[0]), "r"(b[1]));
}

__device__ __forceinline__ void tree_barrier(unsigned* bar, int bid, int tid,
                                             unsigned step1, unsigned perCtr) {
    if (tid == 0) atomicAdd(&bar[(bid & 7) * 32], 1u);
    if (tid < 8) {
        unsigned tgt = step1 * perCtr;
        while (*(volatile unsigned*)&bar[tid * 32] < tgt) {}
    }
    __syncthreads();
}

// ---- bf16 split stores (recurrence state only) ----
__device__ __forceinline__ void split_store_pair(unsigned char* st, int nCh, int blk,
                                                 int row, int kp, float v0, float v1) {
    int chunk = kp >> 6, kin = kp & 63;
    size_t base = ((size_t)(blk * nCh + chunk)) * PAIR_BYTES;
    unsigned so = swz((unsigned)(row * 128 + kin * 2));
    __nv_bfloat16 h0 = __float2bfloat16(v0), h1 = __float2bfloat16(v1);
    __nv_bfloat16 l0 = __float2bfloat16(v0 - __bfloat162float(h0));
    __nv_bfloat16 l1 = __float2bfloat16(v1 - __bfloat162float(h1));
    *(unsigned*)(st + base + so) =
        (unsigned)__bfloat16_as_ushort(h0) | ((unsigned)__bfloat16_as_ushort(h1) << 16);
    *(unsigned*)(st + base + TILE_BYTES + so) =
        (unsigned)__bfloat16_as_ushort(l0) | ((unsigned)__bfloat16_as_ushort(l1) << 16);
}
__device__ __forceinline__ void split_store_half(unsigned char* tileBase, int row, int kin,
                                                 float v) {
    unsigned so = swz((unsigned)(row * 128 + kin * 2));
    __nv_bfloat16 hi = __float2bfloat16(v);
    __nv_bfloat16 lo = __float2bfloat16(v - __bfloat162float(hi));
    *(unsigned short*)(tileBase + so) = __bfloat16_as_ushort(hi);
    *(unsigned short*)(tileBase + TILE_BYTES + so) = __bfloat16_as_ushort(lo);
}
// ---- fp16 single stores (GEMM staging) ----
__device__ __forceinline__ void h16_store_pair(unsigned char* st, int nCh, int blk,
                                               int row, int kp, float v0, float v1) {
    int chunk = kp >> 6, kin = kp & 63;
    size_t base = ((size_t)(blk * nCh + chunk)) * TILE_BYTES;
    unsigned so = swz((unsigned)(row * 128 + kin * 2));
    __half h0 = __float2half(v0), h1 = __float2half(v1);
    *(unsigned*)(st + base + so) =
        (unsigned)__half_as_ushort(h0) | ((unsigned)__half_as_ushort(h1) << 16);
}
__device__ __forceinline__ void h16_store_one(unsigned char* tileBase, int row, int kin,
                                              float v) {
    unsigned so = swz((unsigned)(row * 128 + kin * 2));
    *(unsigned short*)(tileBase + so) = __half_as_ushort(__float2half(v));
}

// ---- prep ----
__device__ __forceinline__ void pack_region(const float* Wh, float* out, int H, long r) {
    long per = 4L * H * H;
    int dir = (int)(r / per);
    long s = r % per;
    int g = (int)(s & 3), jj = (int)((s >> 2) % H), k = (int)(s / (4 * H));
    out[dir * per + s] = Wh[dir * per + (size_t)(g * H + jj) * H + k];
}
#define R_SWH 524288L
#define R_DWS 2097152L
#define R_WB 2097152L
#define R_BW0 1179648L
#define R_BW1 2097152L
#define R_BQ 262144L
#define R_BDEC 3276800L
#define R_CEMB 131072L
#define R_PAD 131072L
#define R_BS0 327680L
#define R_BS1 524288L
#define R_EMBS 81920L
#define R_DLAB 262144L
#define R_CLS 15360L
#define PREP_BLOCKS 52860

__global__ void prep_kernel(const float* __restrict__ sWh0, const float* __restrict__ sWh1,
                            const float* __restrict__ wWh0, const float* __restrict__ wWh1,
                            const float* __restrict__ dWh, const float* __restrict__ wWx0,
                            const float* __restrict__ wWx1, const float* __restrict__ Wq,
                            const float* __restrict__ dWx, const int* __restrict__ words,
                            const float* __restrict__ char_table, const int* __restrict__ sents,
                            const float* __restrict__ word_embs, const int* __restrict__ labels,
                            const float* __restrict__ clsW, const float* __restrict__ sWx0,
                            const float* __restrict__ sWx1) {
    if (blockIdx.x == 0 && threadIdx.x < 8) {
        g_barT[threadIdx.x * 32] = 0u;
        g_barT2[threadIdx.x * 32] = 0u;
        g_barT3[threadIdx.x * 32] = 0u;
    }
    long idx = (long)blockIdx.x * 256 + threadIdx.x;
    if (idx < R_SWH) { pack_region(sWh0, g_sWh0P, SH_, idx); return; }
    idx -= R_SWH;
    if (idx < R_SWH) { pack_region(sWh1, g_sWh1P, SH_, idx); return; }
    idx -= R_SWH;
    if (idx < R_DWS) {
        int n = (int)(idx / 512), kp = 2 * (int)(idx % 512);
        split_store_pair(g_stDWr, 16, n >> 7, n & 127, kp,
                         dWh[(size_t)n * 1024 + kp], dWh[(size_t)n * 1024 + kp + 1]);
        return;
    }
    idx -= R_DWS;
    if (idx < R_WB) {
        int ld = (int)(idx >> 19);
        long e = idx & ((1L << 19) - 1);
        int r = (int)(e >> 8);
        int kp = 2 * (int)(e & 255);
        int g = r & 3, j = r >> 2;
        const float* Ws = (ld >> 1) ? wWh1 : wWh0;
        const float* w = Ws + (size_t)(ld & 1) * 4 * 512 * 512 + (size_t)(g * 512 + j) * 512;
        split_store_pair(g_stWw + (size_t)ld * 16 * 8 * PAIR_BYTES, 8, r >> 7, r & 127, kp,
                         w[kp], w[kp + 1]);
        return;
    }
    idx -= R_WB;
    if (idx < R_BW0) {
        int n = (int)(idx / 288), kp = 2 * (int)(idx % 288);
        float v0 = (kp < 544) ? wWx0[(size_t)n * 544 + kp] : 0.f;
        float v1 = (kp + 1 < 544) ? wWx0[(size_t)n * 544 + kp + 1] : 0.f;
        h16_store_pair(g_stB_w0, NCH_W0, n >> 7, n & 127, kp, v0, v1);
        return;
    }
    idx -= R_BW0;
    if (idx < R_BW1) {
        int n = (int)(idx / 512), kp = 2 * (int)(idx % 512);
        h16_store_pair(g_stB_w1, NCH_W1, n >> 7, n & 127, kp,
                       wWx1[(size_t)n * 1024 + kp], wWx1[(size_t)n * 1024 + kp + 1]);
        return;
    }
    idx -= R_BW1;
    if (idx < R_BQ) {
        int n = (int)(idx / 512), kp = 2 * (int)(idx % 512);
        h16_store_pair(g_stB_q, NCH_Q, n >> 7, n & 127, kp,
                       Wq[(size_t)kp * 512 + n], Wq[(size_t)(kp + 1) * 512 + n]);
        return;
    }
    idx -= R_BQ;
    if (idx < R_BDEC) {
        int n = (int)(idx / 800), kp = 2 * (int)(idx % 800);
        float v0 = (kp < 1544) ? dWx[(size_t)n * 1544 + kp] : 0.f;
        float v1 = (kp + 1 < 1544) ? dWx[(size_t)n * 1544 + kp + 1] : 0.f;
        h16_store_pair(g_stB_dec, NCH_DEC, n >> 7, n & 127, kp, v0, v1);
        return;
    }
    idx -= R_BDEC;
    if (idx < R_CEMB) {
        int r = (int)(idx / 16), kp = 2 * (int)(idx % 16);
        int w = words[r];
        h16_store_pair(g_stageA, NCH_W0, r >> 7, r & 127, kp,
                       char_table[w * 32 + kp], char_table[w * 32 + kp + 1]);
        return;
    }
    idx -= R_CEMB;
    if (idx < R_PAD) {
        int r = (int)(idx / 16), kp = 544 + 2 * (int)(idx % 16);
        h16_store_pair(g_stageA, NCH_W0, r >> 7, r & 127, kp, 0.f, 0.f);
        return;
    }
    idx -= R_PAD;
    if (idx < R_BS0) {
        int n = (int)(idx / 160), kp = 2 * (int)(idx % 160);
        int dir = n >> 10, j = n & 1023;
        const float* w = sWx0 + (size_t)dir * 1024 * 300 + (size_t)j * 300;
        float v0 = (kp < 300) ? w[kp] : 0.f;
        float v1 = (kp + 1 < 300) ? w[kp + 1] : 0.f;
        h16_store_pair(g_stB_s0, 5, n >> 7, n & 127, kp, v0, v1);
        return;
    }
    idx -= R_BS0;
    if (idx < R_BS1) {
        int n = (int)(idx / 256), kp = 2 * (int)(idx % 256);
        int dir = n >> 10, j = n & 1023;
        const float* w = sWx1 + (size_t)dir * 1024 * 512 + (size_t)j * 512;
        h16_store_pair(g_stB_s1, 8, n >> 7, n & 127, kp, w[kp], w[kp + 1]);
        return;
    }
    idx -= R_BS1;
    if (idx < R_EMBS) {
        int r = (int)(idx / 160), kp = 2 * (int)(idx % 160);
        const float* e = word_embs + (size_t)sents[r] * 300;
        float v0 = (kp < 300) ? e[kp] : 0.f;
        float v1 = (kp + 1 < 300) ? e[kp + 1] : 0.f;
        h16_store_pair(g_stageS, 5, r >> 7, r & 127, kp, v0, v1);
        return;
    }
    idx -= R_EMBS;
    if (idx < R_DLAB) {
        int r = (int)(idx / 32), kp = 1536 + 2 * (int)(idx % 32);
        float v0 = (kp < 1544) ? (float)labels[r * 8 + (kp - 1536)] : 0.f;
        float v1 = (kp + 1 < 1544) ? (float)labels[r * 8 + (kp + 1 - 1536)] : 0.f;
        h16_store_pair(g_stageD, NCH_DEC, r >> 7, r & 127, kp, v0, v1);
        return;
    }
    idx -= R_DLAB;
    if (idx < R_CLS) {
        int n = (int)(idx / 1024), k = (int)(idx % 1024);
        g_clsWT[n * 1024 + k] = clsW[(size_t)k * 15 + n];
    }
}

// ---- HMMA GEMM: fp16 single-pass, 512 threads, 3-stage bulk pipeline ----
__global__ void __launch_bounds__(512) tgemm_kernel(
    const unsigned char* __restrict__ stA, const unsigned char* __restrict__ stB,
    const float* __restrict__ bias, float* __restrict__ C, int N, int nCh) {
    extern __shared__ unsigned char smraw[];
    uint32_t smb = smem_u32(smraw);
    uint32_t ab = (smb + 1023) & ~1023u;
    uint32_t ctrl = ab + 98304;
    int tid = threadIdx.x, lane = tid & 31, wid = tid >> 5;
    int wm = wid & 3, wn = wid >> 2;
    int nb = blockIdx.x, mb = blockIdx.y;

    if (tid == 0) {
        mbar_init(ctrl, 1);
        mbar_init(ctrl + 8, 1);
        mbar_init(ctrl + 16, 1);
        fence_async();
    }
    __syncthreads();

    float acc[2][4][4];
#pragma unroll
    for (int i = 0; i < 2; ++i)
#pragma unroll
        for (int j = 0; j < 4; ++j)
#pragma unroll
            for (int k = 0; k < 4; ++k) acc[i][j][k] = 0.f;

    int ar = (lane & 7) + ((lane >> 3) & 1) * 8;
    int ac = (lane >> 4) * 16;
    int br = (lane & 7) + ((lane >> 4) & 1) * 8;
    int bc = ((lane >> 3) & 1) * 16;

    auto issue = [&](int c) {
        if (tid == 0) {
            int buf = c % 3;
            uint32_t bar = ctrl + buf * 8;
            uint32_t dst = ab + buf * 32768;
            mbar_expect_tx(bar, 32768u);
            cp_bulk(dst, stA + ((size_t)mb * nCh + c) * TILE_BYTES, 16384u, bar);
            cp_bulk(dst + 16384, stB + ((size_t)nb * nCh + c) * TILE_BYTES, 16384u, bar);
        }
    };

    issue(0);
    if (nCh > 1) issue(1);
    if (nCh > 2) issue(2);
    for (int c = 0; c < nCh; ++c) {
        int buf = c % 3;
        mbar_wait(ctrl + buf * 8, (c / 3) & 1);
        uint32_t base = ab + buf * 32768;
#pragma unroll
        for (int ks = 0; ks < 4; ++ks) {
            uint32_t ah[2][4], bh[2][4];
#pragma unroll
            for (int mf = 0; mf < 2; ++mf) {
                uint32_t off = swz((unsigned)((wm * 32 + mf * 16 + ar) * 128 + ac + ks * 32));
                ldm_x4(ah[mf], base + off);
            }
#pragma unroll
            for (int nf2 = 0; nf2 < 2; ++nf2) {
                uint32_t off = swz((unsigned)((wn * 32 + nf2 * 16 + br) * 128 + bc + ks * 32));
                ldm_x4(bh[nf2], base + 16384 + off);
            }
#pragma unroll
            for (int mf = 0; mf < 2; ++mf)
#pragma unroll
                for (int nf = 0; nf < 4; ++nf)
                    mmah16816(acc[mf][nf], ah[mf], &bh[nf >> 1][(nf & 1) * 2]);
        }
        __syncthreads();
        if (c + 3 < nCh) issue(c + 3);
    }
#pragma unroll
    for (int mf = 0; mf < 2; ++mf) {
#pragma unroll
        for (int nf = 0; nf < 4; ++nf) {
            int row = mb * 128 + wm * 32 + mf * 16 + (lane >> 2);
            int col = nb * 128 + wn * 32 + nf * 8 + (lane & 3) * 2;
            float b0 = bias ? bias[col] : 0.f;
            float b1 = bias ? bias[col + 1] : 0.f;
            float2 v0 = make_float2(acc[mf][nf][0] + b0, acc[mf][nf][1] + b1);
            float2 v1 = make_float2(acc[mf][nf][2] + b0, acc[mf][nf][3] + b1);
            *(float2*)(C + (size_t)row * N + col) = v0;
            *(float2*)(C + (size_t)(row + 8) * N + col) = v1;
        }
    }
}

// ---- persistent HMMA word-LSTM recurrence (split-bf16, unchanged core) ----
__global__ void __launch_bounds__(256) wordrec_kernel(
    const unsigned char* __restrict__ stW, const float* __restrict__ pre,
    int writeDec, int base) {
    extern __shared__ unsigned char dsm[];
    uint32_t smb = smem_u32(dsm);
    uint32_t wctrl = smb + 131072 + 98304;
    int tid = threadIdx.x, lane = tid & 31, wid = tid >> 5;
    int wm = wid & 1, wn = wid >> 1;
    int bid = blockIdx.x;
    int dir = bid >> 6, r6 = bid & 63, mb = r6 >> 4, nt = r6 & 15;

    if (tid == 0) {
        mbar_init(wctrl, 1);
        mbar_init(wctrl + 8, 1);
        fence_async();
    }
    {
        const unsigned char* wb = stW + ((size_t)(dir * 16 + nt)) * 8 * PAIR_BYTES;
        uint4* dst = (uint4*)dsm;
#pragma unroll 4
        for (int i = tid; i < 8192; i += 256) {
            int c = i >> 10, w = i & 1023;
            dst[i] = *(const uint4*)(wb + (size_t)c * PAIR_BYTES + w * 16);
        }
    }
    __syncthreads();

    int ar = (lane & 7) + ((lane >> 3) & 1) * 8;
    int ac = (lane >> 4) * 16;
    int br = (lane & 7) + ((lane >> 4) & 1) * 8;
    int bc = ((lane >> 3) & 1) * 16;

    float cacc[4][4][2];
#pragma unroll
    for (int a = 0; a < 4; ++a)
#pragma unroll
        for (int b = 0; b < 4; ++b) { cacc[a][b][0] = 0.f; cacc[a][b][1] = 0.f; }

    int ph0 = 0, ph1 = 0;

    for (int t = 0; t < 16; ++t) {
        int rb = t & 1, wbuf = rb ^ 1;
        int tdir = dir ? (15 - t) : t;

        auto issueW = [&](int c) {
            if (tid == 0) {
                int buf = c & 1;
                uint32_t bar = wctrl + buf * 8;
                uint32_t dst = smb + 131072 + buf * 49152;
                mbar_expect_tx(bar, 49152u);
                cp_bulk(dst,
                        g_hstage + (((size_t)((dir * 2 + rb) * 4 + mb)) * 8 + c) * PAIR_BYTES,
                        32768u, bar);
                cp_bulk(dst + 32768,
                        stW + (((size_t)(dir * 16 + nt)) * 8 + c) * PAIR_BYTES + TILE_BYTES,
                        16384u, bar);
            }
        };

        float acc[4][4][4];
#pragma unroll
        for (int a = 0; a < 4; ++a)
#pragma unroll
            for (int b = 0; b < 4; ++b)
#pragma unroll
                for (int k = 0; k < 4; ++k) acc[a][b][k] = 0.f;

        if (t > 0) {
            issueW(0);
            issueW(1);
            for (int c = 0; c < 8; ++c) {
                int buf = c & 1;
                mbar_wait(wctrl + buf * 8, buf ? ph1 : ph0);
                if (buf) ph1 ^= 1; else ph0 ^= 1;
                uint32_t sb = smb + 131072 + buf * 49152;
                uint32_t bhb = smb + c * 16384;
#pragma unroll
                for (int ks = 0; ks < 4; ++ks) {
                    uint32_t ah[4][4], al[4][4], bh[2][4], bl[2][4];
#pragma unroll
                    for (int mf = 0; mf < 4; ++mf) {
                        uint32_t off = swz((unsigned)((wm * 64 + mf * 16 + ar) * 128 + ac + ks * 32));
                        ldm_x4(ah[mf], sb + off);
                        ldm_x4(al[mf], sb + 16384 + off);
                    }
#pragma unroll
                    for (int nf2 = 0; nf2 < 2; ++nf2) {
                        uint32_t off = swz((unsigned)((wn * 32 + nf2 * 16 + br) * 128 + bc + ks * 32));
                        ldm_x4(bh[nf2], bhb + off);
                        ldm_x4(bl[nf2], sb + 32768 + off);
                    }
#pragma unroll
                    for (int mf = 0; mf < 4; ++mf)
#pragma unroll
                        for (int nf = 0; nf < 4; ++nf) {
                            mma16816(acc[mf][nf], ah[mf], &bh[nf >> 1][(nf & 1) * 2]);
                            mma16816(acc[mf][nf], ah[mf], &bl[nf >> 1][(nf & 1) * 2]);
                            mma16816(acc[mf][nf], al[mf], &bh[nf >> 1][(nf & 1) * 2]);
                        }
                }
                __syncthreads();
                if (c + 2 < 8) issueW(c + 2);
            }
        }

#pragma unroll
        for (int mf = 0; mf < 4; ++mf)
#pragma unroll
            for (int nf = 0; nf < 4; ++nf) {
                float p0 = __shfl_xor_sync(0xffffffffu, acc[mf][nf][0], 1);
                float p1 = __shfl_xor_sync(0xffffffffu, acc[mf][nf][1], 1);
                float p2 = __shfl_xor_sync(0xffffffffu, acc[mf][nf][2], 1);
                float p3 = __shfl_xor_sync(0xffffffffu, acc[mf][nf][3], 1);
                if (!(lane & 1)) {
                    int j = nt * 32 + wn * 8 + nf * 2 + ((lane & 3) >> 1);
                    int r0 = wm * 64 + mf * 16 + (lane >> 2);
#pragma unroll
                    for (int rr = 0; rr < 2; ++rr) {
                        int r = r0 + rr * 8;
                        int n = mb * 128 + r;
                        size_t pb = (size_t)(n * 16 + tdir) * 4096 + dir * 2048 + j;
                        float ai = (rr ? acc[mf][nf][2] : acc[mf][nf][0]) + pre[pb];
                        float af = (rr ? acc[mf][nf][3] : acc[mf][nf][1]) + pre[pb + 512];
                        float ag = (rr ? p2 : p0) + pre[pb + 1024];
                        float ao = (rr ? p3 : p1) + pre[pb + 1536];
                        float cv = cacc[mf][nf][rr];
                        cv = sigm(af) * cv + sigm(ai) * tanhf(ag);
                        float hn = sigm(ao) * tanhf(cv);
                        cacc[mf][nf][rr] = cv;
                        split_store_half(
                            g_hstage + (((size_t)((dir * 2 + wbuf) * 4 + mb)) * 8 + (j >> 6)) * PAIR_BYTES,
                            r, j & 63, hn);
                        int rA = n * 16 + tdir, kp = dir * 512 + j;
                        h16_store_one(
                            g_stageA + (((size_t)(rA >> 7) * 16 + (kp >> 6))) * TILE_BYTES,
                            rA & 127, kp & 63, hn);
                        if (writeDec) {
                            int kp2 = 512 + kp;
                            h16_store_one(
                                g_stageD + (((size_t)(rA >> 7) * 25 + (kp2 >> 6))) * TILE_BYTES,
                                rA & 127, kp2 & 63, hn);
                        }
                    }
                }
            }
        __threadfence();
        __syncthreads();
        tree_barrier(g_barT2, bid, tid, (unsigned)(base + t + 1), 16u);
    }
}

// ---- persistent HMMA decoder (split-bf16, unchanged) ----
__global__ void __launch_bounds__(256) dec_persist_kernel(
    const float* __restrict__ pre, float* __restrict__ dout) {
    extern __shared__ unsigned char dsm[];
    uint32_t smb = smem_u32(dsm);
    int tid = threadIdx.x, lane = tid & 31, w = tid >> 5;
    int bid = blockIdx.x;
    {
        const uint4* src = (const uint4*)g_stDWr;
        uint4* dst = (uint4*)dsm;
#pragma unroll 4
        for (int it = 0; it < 32; ++it) {
            int flat = tid + it * 256;
            int q = flat & 7;
            int ru = flat >> 3;
            int i = ru & 7;
            int hl = (ru >> 3) & 1;
            int g = (ru >> 4) & 3;
            int c = ru >> 6;
            size_t sb = ((((size_t)(g * 8 + (bid >> 4)) * 16 + c) * PAIR_BYTES
                         + (size_t)hl * TILE_BYTES
                         + (size_t)((bid & 15) * 8 + i) * 128) >> 4) + q;
            int db = ((c * 8192 + hl * 4096 + (g * 8 + i) * 128) >> 4) + q;
            dst[db] = src[sb];
        }
    }
    __syncthreads();

    float* red = (float*)(dsm + 131072);
    const unsigned* hHr[2] = {(const unsigned*)&g_hsplitH[0][0], (const unsigned*)&g_hsplitH[1][0]};
    const unsigned* hLr[2] = {(const unsigned*)&g_hsplitL[0][0], (const unsigned*)&g_hsplitL[1][0]};

    int bb = tid >> 3, hh = tid & 7;
    int j = bid * 8 + hh;
    float cc = 0.f;

    int br = (lane & 7) + ((lane >> 4) & 1) * 8;
    int bc = ((lane >> 3) & 1) * 16;
    int k0base = w * 128;

    for (int t = 0; t < 256; ++t) {
        int rb = t & 1;
        const float* p = pre + ((size_t)bb * 256 + t) * 4096 + j;
        float px0 = p[0], px1 = p[1024], px2 = p[2048], px3 = p[3072];

        float acc[2][4][4];
#pragma unroll
        for (int m = 0; m < 2; ++m)
#pragma unroll
            for (int g = 0; g < 4; ++g)
#pragma unroll
                for (int r4 = 0; r4 < 4; ++r4) acc[m][g][r4] = 0.f;

        if (t > 0) {
#pragma unroll 2
            for (int kf = 0; kf < 8; ++kf) {
                int k0 = k0base + kf * 16;
                uint32_t ah[2][4], al[2][4];
#pragma unroll
                for (int m = 0; m < 2; ++m) {
                    int base2 = ((m * 16 + (lane >> 2)) * 1024 + k0) / 2 + (lane & 3);
                    ah[m][0] = __ldcg(hHr[rb] + base2);
                    ah[m][1] = __ldcg(hHr[rb] + base2 + 4096);
                    ah[m][2] = __ldcg(hHr[rb] + base2 + 4);
                    ah[m][3] = __ldcg(hHr[rb] + base2 + 4100);
                    al[m][0] = __ldcg(hLr[rb] + base2);
                    al[m][1] = __ldcg(hLr[rb] + base2 + 4096);
                    al[m][2] = __ldcg(hLr[rb] + base2 + 4);
                    al[m][3] = __ldcg(hLr[rb] + base2 + 4100);
                }
                int chunk = k0 >> 6, kin = k0 & 63;
                uint32_t cbs = smb + chunk * 8192;
                uint32_t bh[2][4], bl[2][4];
#pragma unroll
                for (int nt = 0; nt < 2; ++nt) {
                    uint32_t off = swz((unsigned)((nt * 16 + br) * 128 + bc + kin * 2));
                    ldm_x4(bh[nt], cbs + off);
                    ldm_x4(bl[nt], cbs + 4096 + off);
                }
#pragma unroll
                for (int m = 0; m < 2; ++m)
#pragma unroll
                    for (int g = 0; g < 4; ++g) {
                        mma16816(acc[m][g], ah[m], &bh[g >> 1][(g & 1) * 2]);
                        mma16816(acc[m][g], ah[m], &bl[g >> 1][(g & 1) * 2]);
                        mma16816(acc[m][g], al[m], &bh[g >> 1][(g & 1) * 2]);
                    }
            }
        }
#pragma unroll
        for (int m = 0; m < 2; ++m)
#pragma unroll
            for (int g = 0; g < 4; ++g)
#pragma unroll
                for (int r4 = 0; r4 < 4; ++r4)
                    red[((w * 2 + m) * 4 + g) * 128 + lane * 4 + r4] = acc[m][g][r4];
        __syncthreads();
        {
            int r = bb & 15, m = bb >> 4;
            int gl = ((r & 7) << 2) | (hh >> 1);
            int rg = (hh & 1) + 2 * ((r >> 3) & 1);
            float gv[4] = {0.f, 0.f, 0.f, 0.f};
#pragma unroll
            for (int w2 = 0; w2 < 8; ++w2)
#pragma unroll
                for (int g = 0; g < 4; ++g)
                    gv[g] += red[((w2 * 2 + m) * 4 + g) * 128 + gl * 4 + rg];
            float ai = gv[0] + px0;
            float af = gv[1] + px1;
            float agg = gv[2] + px2;
            float ao = gv[3] + px3;
            cc = sigm(af) * cc + sigm(ai) * tanhf(agg);
            float hn = sigm(ao) * tanhf(cc);
            dout[((size_t)bb * 256 + t) * 1024 + j] = hn;
            __nv_bfloat16 hi = __float2bfloat16(hn);
            __nv_bfloat16 lo = __float2bfloat16(hn - __bfloat162float(hi));
            g_hsplitH[rb ^ 1][bb * 1024 + j] = hi;
            g_hsplitL[rb ^ 1][bb * 1024 + j] = lo;
        }
        __threadfence();
        __syncthreads();
        tree_barrier(g_barT, bid, tid, (unsigned)(t + 1), 16u);
    }
}

// ---- persistent sentence BiLSTM recurrence ----
template <int MODE>
__global__ void __launch_bounds__(256) sentrec_kernel(
    const float* __restrict__ pre, const float* __restrict__ WhP,
    float* __restrict__ out, const int* __restrict__ words, int base) {
    extern __shared__ unsigned char sms[];
    float4* wS = (float4*)sms;
    float* hsm = (float*)(sms + 65536);
    float* wm = (float*)(sms + 65536 + 16384);
    int tid = threadIdx.x, bid = blockIdx.x;
    int dir = bid >> 5, jb = (bid >> 1) & 15, sb = bid & 1;
    int jl = tid & 15, sq = tid >> 4;
    int s = sb * 16 + sq;
    int j = jb * 16 + jl;

    const float4* Wsrc = (const float4*)(WhP + (size_t)dir * (256 * 256 * 4));
    for (int i = tid; i < 4096; i += 256) {
        int k = i >> 4;
        wS[i] = Wsrc[k * 256 + jb * 16 + (i & 15)];
    }
    if (MODE == 1) {
        for (int x = tid; x < 4096; x += 256)
            wm[x] = (words[(sb * 16 + (x >> 8)) * 256 + (x & 255)] != 0) ? 1.f : 0.f;
    }
    float cc = 0.f;
    __syncthreads();

    for (int tt = 0; tt < 16; ++tt) {
        int rb = tt & 1;
        int t = dir ? (15 - tt) : tt;
        if (tt > 0) {
            const float4* src = (const float4*)(g_shs + ((rb * 2 + dir) * 32 + sb * 16) * 256);
            float4* dst = (float4*)hsm;
#pragma unroll
            for (int i = 0; i < 4; ++i) dst[tid + i * 256] = __ldcg(src + tid + i * 256);
            __syncthreads();
        }
        size_t pb = ((size_t)(s * 16 + t) * 2 + dir) * 1024 + j;
        float ai = pre[pb], af = pre[pb + 256], ag = pre[pb + 512], ao = pre[pb + 768];
        if (tt > 0) {
#pragma unroll 8
            for (int k = 0; k < 256; ++k) {
                float4 w = wS[k * 16 + jl];
                float hk = hsm[sq * 256 + k];
                ai += hk * w.x; af += hk * w.y; ag += hk * w.z; ao += hk * w.w;
            }
        }
        float cv = sigm(af) * cc + sigm(ai) * tanhf(ag);
        float hn = sigm(ao) * tanhf(cv);
        cc = cv;
        g_shs[(((rb ^ 1) * 2 + dir) * 32 + s) * 256 + j] = hn;
        if (MODE == 0) {
            int r = s * 16 + t, kp = dir * 256 + j;
            h16_store_one(g_stageS2 + ((size_t)((r >> 7) * 8 + (kp >> 6))) * TILE_BYTES,
                          r & 127, kp & 63, hn);
        } else {
            out[((size_t)s * 16 + t) * 512 + dir * 256 + j] = hn;
            float v1 = __shfl_down_sync(0xffffffffu, hn, 1);
            if (!(jl & 1)) {
                int kp = 32 + dir * 256 + j;
                int rbrow = (s * 16 + t) * 16;
                int blk = rbrow >> 7;
#pragma unroll
                for (int tw = 0; tw < 16; ++tw) {
                    float m = wm[sq * 256 + t * 16 + tw];
                    h16_store_pair(g_stageA, NCH_W0, blk, (rbrow & 127) + tw, kp, hn * m, v1 * m);
                }
            }
        }
        __threadfence();
        __syncthreads();
        tree_barrier(g_barT3, bid, tid, (unsigned)(base + tt + 1), 8u);
    }
}

// ---- attention ----
__global__ void attention_kernel(const float* __restrict__ q, const float* __restrict__ sent_enc,
                                 const int* __restrict__ words, float* __restrict__ map_out) {
    int bi = blockIdx.x, b = bi >> 4, i = bi & 15;
    __shared__ float se[16 * 513];
    __shared__ float sc[16][16];
    __shared__ float mp[16][16];
    __shared__ int kv[16];
    for (int x = threadIdx.x; x < 16 * 512; x += 256) {
        int jj = x >> 9, d = x & 511;
        se[jj * 513 + d] = sent_enc[((size_t)b * 16 + jj) * 512 + d];
    }
    if (threadIdx.x < 16) {
        int jj = threadIdx.x, any = 0;
        for (int tw = 0; tw < 16; ++tw) any |= (words[(b * 16 + jj) * 16 + tw] != 0);
        kv[jj] = any;
    }
    __syncthreads();
    {
        int cdx = threadIdx.x >> 4, jj = threadIdx.x & 15;
        const float* qr = q + ((size_t)bi * 16 + cdx) * 512;
        const float* ser = se + jj * 513;
        float s = 0.f;
#pragma unroll 4
        for (int d = 0; d < 512; ++d) s += qr[d] * ser[d];
        sc[cdx][jj] = s;
    }
    __syncthreads();
    if (threadIdx.x < 16) {
        int cdx = threadIdx.x;
        float v[16], m = -1e30f;
#pragma unroll
        for (int jj = 0; jj < 16; ++jj) {
            bool valid = (kv[jj] != 0) && (jj != i);
            v[jj] = valid ? sc[cdx][jj] : -1e9f;
            m = fmaxf(m, v[jj]);
        }
        float sum = 0.f;
#pragma unroll
        for (int jj = 0; jj < 16; ++jj) { v[jj] = expf(v[jj] - m); sum += v[jj]; }
        float inv = 1.f / sum;
#pragma unroll
        for (int jj = 0; jj < 16; ++jj) mp[cdx][jj] = v[jj] * inv;
    }
    __syncthreads();
    if (map_out != nullptr && threadIdx.x < 256) {
        int x = threadIdx.x;
        map_out[(size_t)bi * 256 + x] = mp[x >> 4][x & 15];
    }
    for (int x = threadIdx.x; x < 16 * 512; x += 256) {
        int cdx = x >> 9, d = x & 511;
        float s = 0.f;
#pragma unroll
        for (int jj = 0; jj < 16; ++jj) s += mp[cdx][jj] * se[jj * 513 + d];
        int r = bi * 16 + cdx;
        h16_store_one(g_stageD + ((size_t)(r >> 7) * 25 + (d >> 6)) * TILE_BYTES,
                      r & 127, d & 63, s);
    }
}

// ---- classifier: warp per row ----
__global__ void __launch_bounds__(256) classifier_kernel(
    const float* __restrict__ dec_out, const float* __restrict__ Wt,
    const float* __restrict__ bias, float* __restrict__ out) {
    __shared__ float res[8][16];
    int w = threadIdx.x >> 5, lane = threadIdx.x & 31;
    int m = blockIdx.x * 8 + w;
    const float4* x4 = (const float4*)(dec_out + (size_t)m * 1024);
    float4 xv[8];
#pragma unroll
    for (int i = 0; i < 8; ++i) xv[i] = x4[lane + i * 32];
#pragma unroll
    for (int n = 0; n < 15; ++n) {
        const float4* w4 = (const float4*)(Wt + n * 1024);
        float s = 0.f;
#pragma unroll
        for (int i = 0; i < 8; ++i) {
            float4 b = w4[lane + i * 32];
            s += xv[i].x * b.x + xv[i].y * b.y + xv[i].z * b.z + xv[i].w * b.w;
        }
#pragma unroll
        for (int o = 16; o; o >>= 1) s += __shfl_xor_sync(0xffffffffu, s, o);
        if (lane == 0) res[w][n] = s + bias[n];
    }
    __syncthreads();
    for (int i = threadIdx.x; i < 120; i += 256) {
        int mr = i / 15, n = i % 15;
        out[(size_t)(blockIdx.x * 8 + mr) * 15 + n] = res[mr][n];
    }
}

// ---- host ----
static void* symp(const void* s) { void* p = nullptr; cudaGetSymbolAddress(&p, s); return p; }

extern "C" void kernel_launch(void* const* d_in, const int* in_sizes, int n_in,
                              void* d_out, int out_size) {
    (void)in_sizes; (void)n_in;
    const int* sents = (const int*)d_in[0];
    const int* words = (const int*)d_in[1];
    const int* labels = (const int*)d_in[2];
    const float* word_embs = (const float*)d_in[3];
    const float* char_table = (const float*)d_in[4];
    const float* sWx0 = (const float*)d_in[5];
    const float* sWh0 = (const float*)d_in[6];
    const float* sb0 = (const float*)d_in[7];
    const float* sWx1 = (const float*)d_in[8];
    const float* sWh1 = (const float*)d_in[9];
    const float* sb1 = (const float*)d_in[10];
    const float* wWx0 = (const float*)d_in[11];
    const float* wWh0 = (const float*)d_in[12];
    const float* wb0 = (const float*)d_in[13];
    const float* wWx1 = (const float*)d_in[14];
    const float* wWh1 = (const float*)d_in[15];
    const float* wb1 = (const float*)d_in[16];
    const float* Wq = (const float*)d_in[17];
    const float* dWx = (const float*)d_in[18];
    const float* dWh = (const float*)d_in[19];
    const float* db = (const float*)d_in[20];
    const float* clsW = (const float*)d_in[21];
    const float* clsb = (const float*)d_in[22];
    float* out = (float*)d_out;

    float* pre_s = (float*)symp(g_pre_s);
    float* sent_enc = (float*)symp(g_sent_enc);
    float* pre_w = (float*)symp(g_pre_w);
    float* qbuf = (float*)symp(g_q);
    float* pre_d = (float*)symp(g_pre_d);
    float* dec_out = (float*)symp(g_dec_out);
    float* sWh0P = (float*)symp(g_sWh0P);
    float* sWh1P = (float*)symp(g_sWh1P);
    float* clsWT = (float*)symp(g_clsWT);
    const unsigned char* stA = (const unsigned char*)symp(g_stageA);
    const unsigned char* stD = (const unsigned char*)symp(g_stageD);
    const unsigned char* stS = (const unsigned char*)symp(g_stageS);
    const unsigned char* stS2 = (const unsigned char*)symp(g_stageS2);
    const unsigned char* stBs0 = (const unsigned char*)symp(g_stB_s0);
    const unsigned char* stBs1 = (const unsigned char*)symp(g_stB_s1);
    const unsigned char* stBw0 = (const unsigned char*)symp(g_stB_w0);
    const unsigned char* stBw1 = (const unsigned char*)symp(g_stB_w1);
    const unsigned char* stBq = (const unsigned char*)symp(g_stB_q);
    const unsigned char* stBdec = (const unsigned char*)symp(g_stB_dec);
    const unsigned char* stWw = (const unsigned char*)symp(g_stWw);

    cudaFuncSetAttribute(tgemm_kernel, cudaFuncAttributeMaxDynamicSharedMemorySize, TG_SMEM);
    cudaFuncSetAttribute(dec_persist_kernel, cudaFuncAttributeMaxDynamicSharedMemorySize, DEC_SMEM);
    cudaFuncSetAttribute(wordrec_kernel, cudaFuncAttributeMaxDynamicSharedMemorySize, WR_SMEM);
    cudaFuncSetAttribute(sentrec_kernel<0>, cudaFuncAttributeMaxDynamicSharedMemorySize, SR_SMEM);
    cudaFuncSetAttribute(sentrec_kernel<1>, cudaFuncAttributeMaxDynamicSharedMemorySize, SR_SMEM);

    const size_t wwLayer = 2ul * 16 * 8 * PAIR_BYTES;

    prep_kernel<<<PREP_BLOCKS, 256>>>(sWh0, sWh1, wWh0, wWh1, dWh, wWx0, wWx1, Wq, dWx,
                                      words, char_table, sents, word_embs, labels, clsW,
                                      sWx0, sWx1);
    tgemm_kernel<<<dim3(16, 4), 512, TG_SMEM>>>(stS, stBs0, sb0, pre_s, 2048, 5);
    sentrec_kernel<0><<<64, 256, SR_SMEM>>>(pre_s, sWh0P, nullptr, nullptr, 0);
    tgemm_kernel<<<dim3(16, 4), 512, TG_SMEM>>>(stS2, stBs1, sb1, pre_s, 2048, 8);
    sentrec_kernel<1><<<64, 256, SR_SMEM>>>(pre_s, sWh1P, sent_enc, words, 16);
    tgemm_kernel<<<dim3(32, 64), 512, TG_SMEM>>>(stA, stBw0, wb0, pre_w, 4096, NCH_W0);
    wordrec_kernel<<<128, 256, WR_SMEM>>>(stWw, pre_w, 0, 0);
    tgemm_kernel<<<dim3(32, 64), 512, TG_SMEM>>>(stA, stBw1, wb1, pre_w, 4096, NCH_W1);
    wordrec_kernel<<<128, 256, WR_SMEM>>>(stWw + wwLayer, pre_w, 1, 16);
    tgemm_kernel<<<dim3(4, 64), 512, TG_SMEM>>>(stA, stBq, nullptr, qbuf, 512, NCH_Q);
    float* map_out = (out_size >= (NR_ * 15 + 131072)) ? (out + NR_ * 15) : nullptr;
    attention_kernel<<<NSEQ_, 256>>>(qbuf, sent_enc, words, map_out);
    tgemm_kernel<<<dim3(32, 64), 512, TG_SMEM>>>(stD, stBdec, db, pre_d, 4096, NCH_DEC);
    dec_persist_kernel<<<128, 256, DEC_SMEM>>>(pre_d, dec_out);
    classifier_kernel<<<NR_ / 8, 256>>>(dec_out, clsWT, clsb, out);
}

// round 16
// speedup vs baseline: 1.6391x; 1.3446x over previous
#include <cuda_runtime.h>
#include <cuda_bf16.h>
#include <cuda_fp16.h>
#include <math.h>
#include <stdint.h>

#define B_ 32
#define SH_ 256
#define WH_ 512
#define DH_ 1024
#define NSEQ_ 512
#define NR_ 8192
#define NCH_W0 9
#define NCH_W1 16
#define NCH_Q 16
#define NCH_DEC 25
#define TILE_BYTES 16384
#define PAIR_BYTES 32768
#define TG_SMEM (3 * 32768 + 1088)
#define DEC_SMEM (65536 + 32768)
#define WR_SMEM (131072 + 2 * 16384 + 64)
#define SR_SMEM (65536 + 16384 + 16384)

#define DEVBUF __device__ __align__(16)
DEVBUF float g_pre_s[NSEQ_ * 2048];
DEVBUF float g_sent_enc[NSEQ_ * 512];
DEVBUF float g_pre_w[NR_ * 4096];
DEVBUF float g_q[NR_ * 512];
DEVBUF float g_pre_d[NR_ * 4096];
DEVBUF float g_dec_out[NR_ * 1024];
DEVBUF float g_sWh0P[2 * SH_ * SH_ * 4];
DEVBUF float g_sWh1P[2 * SH_ * SH_ * 4];
DEVBUF float g_clsWT[15 * 1024];
DEVBUF float g_shs[2 * 2 * 32 * 256];
// fp16 staging (GEMMs + recurrence weights/state)
DEVBUF unsigned char g_stageA[64ul * 16 * TILE_BYTES];
DEVBUF unsigned char g_stageD[64ul * 25 * TILE_BYTES];
DEVBUF unsigned char g_stageS[4ul * 5 * TILE_BYTES];
DEVBUF unsigned char g_stageS2[4ul * 8 * TILE_BYTES];
DEVBUF unsigned char g_stB_s0[16ul * 5 * TILE_BYTES];
DEVBUF unsigned char g_stB_s1[16ul * 8 * TILE_BYTES];
DEVBUF unsigned char g_stB_w0[32ul * NCH_W0 * TILE_BYTES];
DEVBUF unsigned char g_stB_w1[32ul * NCH_W1 * TILE_BYTES];
DEVBUF unsigned char g_stB_q[4ul * NCH_Q * TILE_BYTES];
DEVBUF unsigned char g_stB_dec[32ul * NCH_DEC * TILE_BYTES];
DEVBUF unsigned char g_stDWr[32ul * 16 * TILE_BYTES];
DEVBUF unsigned char g_stWw[4ul * 16 * 8 * TILE_BYTES];
DEVBUF unsigned char g_hstage[128ul * TILE_BYTES];
DEVBUF __half g_hsplit[2][B_ * DH_];
DEVBUF unsigned g_barT[8 * 32];
DEVBUF unsigned g_barT2[8 * 32];
DEVBUF unsigned g_barT3[8 * 32];

__device__ __forceinline__ float sigm(float x) { return 1.f / (1.f + expf(-x)); }
__device__ __forceinline__ unsigned swz(unsigned o) { return o ^ ((o >> 3) & 0x70); }

__device__ __forceinline__ uint32_t smem_u32(const void* p) {
    uint32_t a;
    asm("{ .reg .u64 t; cvta.to.shared.u64 t, %1; cvt.u32.u64 %0, t; }" : "=r"(a) : "l"(p));
    return a;
}
__device__ __forceinline__ void cp_bulk(uint32_t dst, const void* src, uint32_t bytes,
                                        uint32_t mbar) {
    asm volatile(
        "cp.async.bulk.shared::cta.global.mbarrier::complete_tx::bytes [%0], [%1], %2, [%3];"
        :: "r"(dst), "l"(src), "r"(bytes), "r"(mbar) : "memory");
}
__device__ __forceinline__ void mbar_init(uint32_t a, uint32_t c) {
    asm volatile("mbarrier.init.shared.b64 [%0], %1;" :: "r"(a), "r"(c) : "memory");
}
__device__ __forceinline__ void mbar_expect_tx(uint32_t a, uint32_t bytes) {
    asm volatile("mbarrier.arrive.expect_tx.shared.b64 _, [%0], %1;"
                 :: "r"(a), "r"(bytes) : "memory");
}
__device__ __forceinline__ void mbar_wait(uint32_t a, uint32_t par) {
    asm volatile(
        "{\n\t.reg .pred P1;\n\tLW%=:\n\t"
        "mbarrier.try_wait.parity.acquire.cta.shared::cta.b64 P1, [%0], %1, 0x989680;\n\t"
        "@P1 bra.uni LD%=;\n\tbra.uni LW%=;\n\tLD%=:\n\t}"
        :: "r"(a), "r"(par) : "memory");
}
__device__ __forceinline__ void fence_async() {
    asm volatile("fence.proxy.async.shared::cta;" ::: "memory");
}
__device__ __forceinline__ void ldm_x4(uint32_t* r, uint32_t addr) {
    asm volatile("ldmatrix.sync.aligned.m8n8.x4.shared.b16 {%0,%1,%2,%3}, [%4];"
                 : "=r"(r[0]), "=r"(r[1]), "=r"(r[2]), "=r"(r[3]) : "r"(addr));
}
__device__ __forceinline__ void mmah16816(float* d, const uint32_t* a, const uint32_t* b) {
    asm volatile(
        "mma.sync.aligned.m16n8k16.row.col.f32.f16.f16.f32 "
        "{%0,%1,%2,%3},{%4,%5,%6,%7},{%8,%9},{%0,%1,%2,%3};"
        : "+f"(d[0]), "+f"(d[1]), "+f"(d[2]), "+f"(d[3])
        : "r"(a[0]), "r"(a[1]), "r"(a[2]), "r"(a[3]), "r"(b[0]), "r"(b[1]));
}

__device__ __forceinline__ void tree_barrier(unsigned* bar, int bid, int tid,
                                             unsigned step1, unsigned perCtr) {
    if (tid == 0) atomicAdd(&bar[(bid & 7) * 32], 1u);
    if (tid < 8) {
        unsigned tgt = step1 * perCtr;
        while (*(volatile unsigned*)&bar[tid * 32] < tgt) {}
    }
    __syncthreads();
}

// ---- fp16 stores into swizzled staging ----
__device__ __forceinline__ void h16_store_pair(unsigned char* st, int nCh, int blk,
                                               int row, int kp, float v0, float v1) {
    int chunk = kp >> 6, kin = kp & 63;
    size_t base = ((size_t)(blk * nCh + chunk)) * TILE_BYTES;
    unsigned so = swz((unsigned)(row * 128 + kin * 2));
    __half h0 = __float2half(v0), h1 = __float2half(v1);
    *(unsigned*)(st + base + so) =
        (unsigned)__half_as_ushort(h0) | ((unsigned)__half_as_ushort(h1) << 16);
}
__device__ __forceinline__ void h16_store_one(unsigned char* tileBase, int row, int kin,
                                              float v) {
    unsigned so = swz((unsigned)(row * 128 + kin * 2));
    *(unsigned short*)(tileBase + so) = __half_as_ushort(__float2half(v));
}

// ---- prep ----
__device__ __forceinline__ void pack_region(const float* Wh, float* out, int H, long r) {
    long per = 4L * H * H;
    int dir = (int)(r / per);
    long s = r % per;
    int g = (int)(s & 3), jj = (int)((s >> 2) % H), k = (int)(s / (4 * H));
    out[dir * per + s] = Wh[dir * per + (size_t)(g * H + jj) * H + k];
}
#define R_SWH 524288L
#define R_DWS 2097152L
#define R_WB 2097152L
#define R_BW0 1179648L
#define R_BW1 2097152L
#define R_BQ 262144L
#define R_BDEC 3276800L
#define R_CEMB 131072L
#define R_PAD 131072L
#define R_BS0 327680L
#define R_BS1 524288L
#define R_EMBS 81920L
#define R_DLAB 262144L
#define R_CLS 15360L
#define PREP_BLOCKS 52860

__global__ void prep_kernel(const float* __restrict__ sWh0, const float* __restrict__ sWh1,
                            const float* __restrict__ wWh0, const float* __restrict__ wWh1,
                            const float* __restrict__ dWh, const float* __restrict__ wWx0,
                            const float* __restrict__ wWx1, const float* __restrict__ Wq,
                            const float* __restrict__ dWx, const int* __restrict__ words,
                            const float* __restrict__ char_table, const int* __restrict__ sents,
                            const float* __restrict__ word_embs, const int* __restrict__ labels,
                            const float* __restrict__ clsW, const float* __restrict__ sWx0,
                            const float* __restrict__ sWx1) {
    if (blockIdx.x == 0 && threadIdx.x < 8) {
        g_barT[threadIdx.x * 32] = 0u;
        g_barT2[threadIdx.x * 32] = 0u;
        g_barT3[threadIdx.x * 32] = 0u;
    }
    long idx = (long)blockIdx.x * 256 + threadIdx.x;
    if (idx < R_SWH) { pack_region(sWh0, g_sWh0P, SH_, idx); return; }
    idx -= R_SWH;
    if (idx < R_SWH) { pack_region(sWh1, g_sWh1P, SH_, idx); return; }
    idx -= R_SWH;
    if (idx < R_DWS) {
        int n = (int)(idx / 512), kp = 2 * (int)(idx % 512);
        h16_store_pair(g_stDWr, 16, n >> 7, n & 127, kp,
                       dWh[(size_t)n * 1024 + kp], dWh[(size_t)n * 1024 + kp + 1]);
        return;
    }
    idx -= R_DWS;
    if (idx < R_WB) {
        int ld = (int)(idx >> 19);
        long e = idx & ((1L << 19) - 1);
        int r = (int)(e >> 8);
        int kp = 2 * (int)(e & 255);
        int g = r & 3, j = r >> 2;
        const float* Ws = (ld >> 1) ? wWh1 : wWh0;
        const float* w = Ws + (size_t)(ld & 1) * 4 * 512 * 512 + (size_t)(g * 512 + j) * 512;
        h16_store_pair(g_stWw + (size_t)ld * 16 * 8 * TILE_BYTES, 8, r >> 7, r & 127, kp,
                       w[kp], w[kp + 1]);
        return;
    }
    idx -= R_WB;
    if (idx < R_BW0) {
        int n = (int)(idx / 288), kp = 2 * (int)(idx % 288);
        float v0 = (kp < 544) ? wWx0[(size_t)n * 544 + kp] : 0.f;
        float v1 = (kp + 1 < 544) ? wWx0[(size_t)n * 544 + kp + 1] : 0.f;
        h16_store_pair(g_stB_w0, NCH_W0, n >> 7, n & 127, kp, v0, v1);
        return;
    }
    idx -= R_BW0;
    if (idx < R_BW1) {
        int n = (int)(idx / 512), kp = 2 * (int)(idx % 512);
        h16_store_pair(g_stB_w1, NCH_W1, n >> 7, n & 127, kp,
                       wWx1[(size_t)n * 1024 + kp], wWx1[(size_t)n * 1024 + kp + 1]);
        return;
    }
    idx -= R_BW1;
    if (idx < R_BQ) {
        int n = (int)(idx / 512), kp = 2 * (int)(idx % 512);
        h16_store_pair(g_stB_q, NCH_Q, n >> 7, n & 127, kp,
                       Wq[(size_t)kp * 512 + n], Wq[(size_t)(kp + 1) * 512 + n]);
        return;
    }
    idx -= R_BQ;
    if (idx < R_BDEC) {
        int n = (int)(idx / 800), kp = 2 * (int)(idx % 800);
        float v0 = (kp < 1544) ? dWx[(size_t)n * 1544 + kp] : 0.f;
        float v1 = (kp + 1 < 1544) ? dWx[(size_t)n * 1544 + kp + 1] : 0.f;
        h16_store_pair(g_stB_dec, NCH_DEC, n >> 7, n & 127, kp, v0, v1);
        return;
    }
    idx -= R_BDEC;
    if (idx < R_CEMB) {
        int r = (int)(idx / 16), kp = 2 * (int)(idx % 16);
        int w = words[r];
        h16_store_pair(g_stageA, NCH_W0, r >> 7, r & 127, kp,
                       char_table[w * 32 + kp], char_table[w * 32 + kp + 1]);
        return;
    }
    idx -= R_CEMB;
    if (idx < R_PAD) {
        int r = (int)(idx / 16), kp = 544 + 2 * (int)(idx % 16);
        h16_store_pair(g_stageA, NCH_W0, r >> 7, r & 127, kp, 0.f, 0.f);
        return;
    }
    idx -= R_PAD;
    if (idx < R_BS0) {
        int n = (int)(idx / 160), kp = 2 * (int)(idx % 160);
        int dir = n >> 10, j = n & 1023;
        const float* w = sWx0 + (size_t)dir * 1024 * 300 + (size_t)j * 300;
        float v0 = (kp < 300) ? w[kp] : 0.f;
        float v1 = (kp + 1 < 300) ? w[kp + 1] : 0.f;
        h16_store_pair(g_stB_s0, 5, n >> 7, n & 127, kp, v0, v1);
        return;
    }
    idx -= R_BS0;
    if (idx < R_BS1) {
        int n = (int)(idx / 256), kp = 2 * (int)(idx % 256);
        int dir = n >> 10, j = n & 1023;
        const float* w = sWx1 + (size_t)dir * 1024 * 512 + (size_t)j * 512;
        h16_store_pair(g_stB_s1, 8, n >> 7, n & 127, kp, w[kp], w[kp + 1]);
        return;
    }
    idx -= R_BS1;
    if (idx < R_EMBS) {
        int r = (int)(idx / 160), kp = 2 * (int)(idx % 160);
        const float* e = word_embs + (size_t)sents[r] * 300;
        float v0 = (kp < 300) ? e[kp] : 0.f;
        float v1 = (kp + 1 < 300) ? e[kp + 1] : 0.f;
        h16_store_pair(g_stageS, 5, r >> 7, r & 127, kp, v0, v1);
        return;
    }
    idx -= R_EMBS;
    if (idx < R_DLAB) {
        int r = (int)(idx / 32), kp = 1536 + 2 * (int)(idx % 32);
        float v0 = (kp < 1544) ? (float)labels[r * 8 + (kp - 1536)] : 0.f;
        float v1 = (kp + 1 < 1544) ? (float)labels[r * 8 + (kp + 1 - 1536)] : 0.f;
        h16_store_pair(g_stageD, NCH_DEC, r >> 7, r & 127, kp, v0, v1);
        return;
    }
    idx -= R_DLAB;
    if (idx < R_CLS) {
        int n = (int)(idx / 1024), k = (int)(idx % 1024);
        g_clsWT[n * 1024 + k] = clsW[(size_t)k * 15 + n];
    }
}

// ---- HMMA GEMM: fp16 single-pass, 512 threads, 3-stage bulk pipeline ----
__global__ void __launch_bounds__(512) tgemm_kernel(
    const unsigned char* __restrict__ stA, const unsigned char* __restrict__ stB,
    const float* __restrict__ bias, float* __restrict__ C, int N, int nCh) {
    extern __shared__ unsigned char smraw[];
    uint32_t smb = smem_u32(smraw);
    uint32_t ab = (smb + 1023) & ~1023u;
    uint32_t ctrl = ab + 98304;
    int tid = threadIdx.x, lane = tid & 31, wid = tid >> 5;
    int wm = wid & 3, wn = wid >> 2;
    int nb = blockIdx.x, mb = blockIdx.y;

    if (tid == 0) {
        mbar_init(ctrl, 1);
        mbar_init(ctrl + 8, 1);
        mbar_init(ctrl + 16, 1);
        fence_async();
    }
    __syncthreads();

    float acc[2][4][4];
#pragma unroll
    for (int i = 0; i < 2; ++i)
#pragma unroll
        for (int j = 0; j < 4; ++j)
#pragma unroll
            for (int k = 0; k < 4; ++k) acc[i][j][k] = 0.f;

    int ar = (lane & 7) + ((lane >> 3) & 1) * 8;
    int ac = (lane >> 4) * 16;
    int br = (lane & 7) + ((lane >> 4) & 1) * 8;
    int bc = ((lane >> 3) & 1) * 16;

    auto issue = [&](int c) {
        if (tid == 0) {
            int buf = c % 3;
            uint32_t bar = ctrl + buf * 8;
            uint32_t dst = ab + buf * 32768;
            mbar_expect_tx(bar, 32768u);
            cp_bulk(dst, stA + ((size_t)mb * nCh + c) * TILE_BYTES, 16384u, bar);
            cp_bulk(dst + 16384, stB + ((size_t)nb * nCh + c) * TILE_BYTES, 16384u, bar);
        }
    };

    issue(0);
    if (nCh > 1) issue(1);
    if (nCh > 2) issue(2);
    for (int c = 0; c < nCh; ++c) {
        int buf = c % 3;
        mbar_wait(ctrl + buf * 8, (c / 3) & 1);
        uint32_t base = ab + buf * 32768;
#pragma unroll
        for (int ks = 0; ks < 4; ++ks) {
            uint32_t ah[2][4], bh[2][4];
#pragma unroll
            for (int mf = 0; mf < 2; ++mf) {
                uint32_t off = swz((unsigned)((wm * 32 + mf * 16 + ar) * 128 + ac + ks * 32));
                ldm_x4(ah[mf], base + off);
            }
#pragma unroll
            for (int nf2 = 0; nf2 < 2; ++nf2) {
                uint32_t off = swz((unsigned)((wn * 32 + nf2 * 16 + br) * 128 + bc + ks * 32));
                ldm_x4(bh[nf2], base + 16384 + off);
            }
#pragma unroll
            for (int mf = 0; mf < 2; ++mf)
#pragma unroll
                for (int nf = 0; nf < 4; ++nf)
                    mmah16816(acc[mf][nf], ah[mf], &bh[nf >> 1][(nf & 1) * 2]);
        }
        __syncthreads();
        if (c + 3 < nCh) issue(c + 3);
    }
#pragma unroll
    for (int mf = 0; mf < 2; ++mf) {
#pragma unroll
        for (int nf = 0; nf < 4; ++nf) {
            int row = mb * 128 + wm * 32 + mf * 16 + (lane >> 2);
            int col = nb * 128 + wn * 32 + nf * 8 + (lane & 3) * 2;
            float b0 = bias ? bias[col] : 0.f;
            float b1 = bias ? bias[col + 1] : 0.f;
            float2 v0 = make_float2(acc[mf][nf][0] + b0, acc[mf][nf][1] + b1);
            float2 v1 = make_float2(acc[mf][nf][2] + b0, acc[mf][nf][3] + b1);
            *(float2*)(C + (size_t)row * N + col) = v0;
            *(float2*)(C + (size_t)(row + 8) * N + col) = v1;
        }
    }
}

// ---- persistent word-LSTM recurrence: fp16 single-pass ----
__global__ void __launch_bounds__(256) wordrec_kernel(
    const unsigned char* __restrict__ stW, const float* __restrict__ pre,
    int writeDec, int base) {
    extern __shared__ unsigned char dsm[];
    uint32_t smb = smem_u32(dsm);
    uint32_t wctrl = smb + 131072 + 32768;
    int tid = threadIdx.x, lane = tid & 31, wid = tid >> 5;
    int wm = wid & 1, wn = wid >> 1;
    int bid = blockIdx.x;
    int dir = bid >> 6, r6 = bid & 63, mb = r6 >> 4, nt = r6 & 15;

    if (tid == 0) {
        mbar_init(wctrl, 1);
        mbar_init(wctrl + 8, 1);
        fence_async();
    }
    {   // cache ALL weight chunks (8 x 16KB fp16)
        const uint4* src = (const uint4*)(stW + ((size_t)(dir * 16 + nt)) * 8 * TILE_BYTES);
        uint4* dst = (uint4*)dsm;
#pragma unroll 4
        for (int i = tid; i < 8192; i += 256) dst[i] = src[i];
    }
    __syncthreads();

    int ar = (lane & 7) + ((lane >> 3) & 1) * 8;
    int ac = (lane >> 4) * 16;
    int br = (lane & 7) + ((lane >> 4) & 1) * 8;
    int bc = ((lane >> 3) & 1) * 16;

    float cacc[4][4][2];
#pragma unroll
    for (int a = 0; a < 4; ++a)
#pragma unroll
        for (int b = 0; b < 4; ++b) { cacc[a][b][0] = 0.f; cacc[a][b][1] = 0.f; }

    int ph0 = 0, ph1 = 0;

    for (int t = 0; t < 16; ++t) {
        int rb = t & 1, wbuf = rb ^ 1;
        int tdir = dir ? (15 - t) : t;

        auto issueW = [&](int c) {
            if (tid == 0) {
                int buf = c & 1;
                uint32_t bar = wctrl + buf * 8;
                uint32_t dst = smb + 131072 + buf * 16384;
                mbar_expect_tx(bar, 16384u);
                cp_bulk(dst,
                        g_hstage + (((size_t)((dir * 2 + rb) * 4 + mb)) * 8 + c) * TILE_BYTES,
                        16384u, bar);
            }
        };

        float acc[4][4][4];
#pragma unroll
        for (int a = 0; a < 4; ++a)
#pragma unroll
            for (int b = 0; b < 4; ++b)
#pragma unroll
                for (int k = 0; k < 4; ++k) acc[a][b][k] = 0.f;

        if (t > 0) {
            issueW(0);
            issueW(1);
            for (int c = 0; c < 8; ++c) {
                int buf = c & 1;
                mbar_wait(wctrl + buf * 8, buf ? ph1 : ph0);
                if (buf) ph1 ^= 1; else ph0 ^= 1;
                uint32_t sb = smb + 131072 + buf * 16384;
                uint32_t bhb = smb + c * 16384;
#pragma unroll
                for (int ks = 0; ks < 4; ++ks) {
                    uint32_t ah[4][4], bh[2][4];
#pragma unroll
                    for (int mf = 0; mf < 4; ++mf) {
                        uint32_t off = swz((unsigned)((wm * 64 + mf * 16 + ar) * 128 + ac + ks * 32));
                        ldm_x4(ah[mf], sb + off);
                    }
#pragma unroll
                    for (int nf2 = 0; nf2 < 2; ++nf2) {
                        uint32_t off = swz((unsigned)((wn * 32 + nf2 * 16 + br) * 128 + bc + ks * 32));
                        ldm_x4(bh[nf2], bhb + off);
                    }
#pragma unroll
                    for (int mf = 0; mf < 4; ++mf)
#pragma unroll
                        for (int nf = 0; nf < 4; ++nf)
                            mmah16816(acc[mf][nf], ah[mf], &bh[nf >> 1][(nf & 1) * 2]);
                }
                __syncthreads();
                if (c + 2 < 8) issueW(c + 2);
            }
        }

#pragma unroll
        for (int mf = 0; mf < 4; ++mf)
#pragma unroll
            for (int nf = 0; nf < 4; ++nf) {
                float p0 = __shfl_xor_sync(0xffffffffu, acc[mf][nf][0], 1);
                float p1 = __shfl_xor_sync(0xffffffffu, acc[mf][nf][1], 1);
                float p2 = __shfl_xor_sync(0xffffffffu, acc[mf][nf][2], 1);
                float p3 = __shfl_xor_sync(0xffffffffu, acc[mf][nf][3], 1);
                if (!(lane & 1)) {
                    int j = nt * 32 + wn * 8 + nf * 2 + ((lane & 3) >> 1);
                    int r0 = wm * 64 + mf * 16 + (lane >> 2);
#pragma unroll
                    for (int rr = 0; rr < 2; ++rr) {
                        int r = r0 + rr * 8;
                        int n = mb * 128 + r;
                        size_t pb = (size_t)(n * 16 + tdir) * 4096 + dir * 2048 + j;
                        float ai = (rr ? acc[mf][nf][2] : acc[mf][nf][0]) + pre[pb];
                        float af = (rr ? acc[mf][nf][3] : acc[mf][nf][1]) + pre[pb + 512];
                        float ag = (rr ? p2 : p0) + pre[pb + 1024];
                        float ao = (rr ? p3 : p1) + pre[pb + 1536];
                        float cv = cacc[mf][nf][rr];
                        cv = sigm(af) * cv + sigm(ai) * tanhf(ag);
                        float hn = sigm(ao) * tanhf(cv);
                        cacc[mf][nf][rr] = cv;
                        h16_store_one(
                            g_hstage + (((size_t)((dir * 2 + wbuf) * 4 + mb)) * 8 + (j >> 6)) * TILE_BYTES,
                            r, j & 63, hn);
                        int rA = n * 16 + tdir, kp = dir * 512 + j;
                        h16_store_one(
                            g_stageA + (((size_t)(rA >> 7) * 16 + (kp >> 6))) * TILE_BYTES,
                            rA & 127, kp & 63, hn);
                        if (writeDec) {
                            int kp2 = 512 + kp;
                            h16_store_one(
                                g_stageD + (((size_t)(rA >> 7) * 25 + (kp2 >> 6))) * TILE_BYTES,
                                rA & 127, kp2 & 63, hn);
                        }
                    }
                }
            }
        __threadfence();
        __syncthreads();
        tree_barrier(g_barT2, bid, tid, (unsigned)(base + t + 1), 16u);
    }
}

// ---- persistent decoder: fp16 single-pass ----
__global__ void __launch_bounds__(256) dec_persist_kernel(
    const float* __restrict__ pre, float* __restrict__ dout) {
    extern __shared__ unsigned char dsm[];
    uint32_t smb = smem_u32(dsm);
    int tid = threadIdx.x, lane = tid & 31, w = tid >> 5;
    int bid = blockIdx.x;
    {   // load fp16 weight slice: 16 chunks x 4KB = 64KB
        const uint4* src = (const uint4*)g_stDWr;
        uint4* dst = (uint4*)dsm;
#pragma unroll 4
        for (int it = 0; it < 16; ++it) {
            int flat = tid + it * 256;
            int q = flat & 7;
            int ru = flat >> 3;
            int i = ru & 7;
            int g = (ru >> 3) & 3;
            int c = ru >> 5;
            size_t sb = ((((size_t)(g * 8 + (bid >> 4)) * 16 + c) * TILE_BYTES
                         + (size_t)((bid & 15) * 8 + i) * 128) >> 4) + q;
            int db = ((c * 4096 + (g * 8 + i) * 128) >> 4) + q;
            dst[db] = src[sb];
        }
    }
    __syncthreads();

    float* red = (float*)(dsm + 65536);
    const unsigned* hHr[2] = {(const unsigned*)&g_hsplit[0][0], (const unsigned*)&g_hsplit[1][0]};

    int bb = tid >> 3, hh = tid & 7;
    int j = bid * 8 + hh;
    float cc = 0.f;

    int br = (lane & 7) + ((lane >> 4) & 1) * 8;
    int bc = ((lane >> 3) & 1) * 16;
    int k0base = w * 128;

    for (int t = 0; t < 256; ++t) {
        int rb = t & 1;
        const float* p = pre + ((size_t)bb * 256 + t) * 4096 + j;
        float px0 = p[0], px1 = p[1024], px2 = p[2048], px3 = p[3072];

        float acc[2][4][4];
#pragma unroll
        for (int m = 0; m < 2; ++m)
#pragma unroll
            for (int g = 0; g < 4; ++g)
#pragma unroll
                for (int r4 = 0; r4 < 4; ++r4) acc[m][g][r4] = 0.f;

        if (t > 0) {
#pragma unroll 2
            for (int kf = 0; kf < 8; ++kf) {
                int k0 = k0base + kf * 16;
                uint32_t ah[2][4];
#pragma unroll
                for (int m = 0; m < 2; ++m) {
                    int base2 = ((m * 16 + (lane >> 2)) * 1024 + k0) / 2 + (lane & 3);
                    ah[m][0] = __ldcg(hHr[rb] + base2);
                    ah[m][1] = __ldcg(hHr[rb] + base2 + 4096);
                    ah[m][2] = __ldcg(hHr[rb] + base2 + 4);
                    ah[m][3] = __ldcg(hHr[rb] + base2 + 4100);
                }
                int chunk = k0 >> 6, kin = k0 & 63;
                uint32_t cbs = smb + chunk * 4096;
                uint32_t bh[2][4];
#pragma unroll
                for (int nt = 0; nt < 2; ++nt) {
                    uint32_t off = swz((unsigned)((nt * 16 + br) * 128 + bc + kin * 2));
                    ldm_x4(bh[nt], cbs + off);
                }
#pragma unroll
                for (int m = 0; m < 2; ++m)
#pragma unroll
                    for (int g = 0; g < 4; ++g)
                        mmah16816(acc[m][g], ah[m], &bh[g >> 1][(g & 1) * 2]);
            }
        }
#pragma unroll
        for (int m = 0; m < 2; ++m)
#pragma unroll
            for (int g = 0; g < 4; ++g)
#pragma unroll
                for (int r4 = 0; r4 < 4; ++r4)
                    red[((w * 2 + m) * 4 + g) * 128 + lane * 4 + r4] = acc[m][g][r4];
        __syncthreads();
        {
            int r = bb & 15, m = bb >> 4;
            int gl = ((r & 7) << 2) | (hh >> 1);
            int rg = (hh & 1) + 2 * ((r >> 3) & 1);
            float gv[4] = {0.f, 0.f, 0.f, 0.f};
#pragma unroll
            for (int w2 = 0; w2 < 8; ++w2)
#pragma unroll
                for (int g = 0; g < 4; ++g)
                    gv[g] += red[((w2 * 2 + m) * 4 + g) * 128 + gl * 4 + rg];
            float ai = gv[0] + px0;
            float af = gv[1] + px1;
            float agg = gv[2] + px2;
            float ao = gv[3] + px3;
            cc = sigm(af) * cc + sigm(ai) * tanhf(agg);
            float hn = sigm(ao) * tanhf(cc);
            dout[((size_t)bb * 256 + t) * 1024 + j] = hn;
            g_hsplit[rb ^ 1][bb * 1024 + j] = __float2half(hn);
        }
        __threadfence();
        __syncthreads();
        tree_barrier(g_barT, bid, tid, (unsigned)(t + 1), 16u);
    }
}

// ---- persistent sentence BiLSTM recurrence ----
template <int MODE>
__global__ void __launch_bounds__(256) sentrec_kernel(
    const float* __restrict__ pre, const float* __restrict__ WhP,
    float* __restrict__ out, const int* __restrict__ words, int base) {
    extern __shared__ unsigned char sms[];
    float4* wS = (float4*)sms;
    float* hsm = (float*)(sms + 65536);
    float* wm = (float*)(sms + 65536 + 16384);
    int tid = threadIdx.x, bid = blockIdx.x;
    int dir = bid >> 5, jb = (bid >> 1) & 15, sb = bid & 1;
    int jl = tid & 15, sq = tid >> 4;
    int s = sb * 16 + sq;
    int j = jb * 16 + jl;

    const float4* Wsrc = (const float4*)(WhP + (size_t)dir * (256 * 256 * 4));
    for (int i = tid; i < 4096; i += 256) {
        int k = i >> 4;
        wS[i] = Wsrc[k * 256 + jb * 16 + (i & 15)];
    }
    if (MODE == 1) {
        for (int x = tid; x < 4096; x += 256)
            wm[x] = (words[(sb * 16 + (x >> 8)) * 256 + (x & 255)] != 0) ? 1.f : 0.f;
    }
    float cc = 0.f;
    __syncthreads();

    for (int tt = 0; tt < 16; ++tt) {
        int rb = tt & 1;
        int t = dir ? (15 - tt) : tt;
        if (tt > 0) {
            const float4* src = (const float4*)(g_shs + ((rb * 2 + dir) * 32 + sb * 16) * 256);
            float4* dst = (float4*)hsm;
#pragma unroll
            for (int i = 0; i < 4; ++i) dst[tid + i * 256] = __ldcg(src + tid + i * 256);
            __syncthreads();
        }
        size_t pb = ((size_t)(s * 16 + t) * 2 + dir) * 1024 + j;
        float ai = pre[pb], af = pre[pb + 256], ag = pre[pb + 512], ao = pre[pb + 768];
        if (tt > 0) {
#pragma unroll 8
            for (int k = 0; k < 256; ++k) {
                float4 w = wS[k * 16 + jl];
                float hk = hsm[sq * 256 + k];
                ai += hk * w.x; af += hk * w.y; ag += hk * w.z; ao += hk * w.w;
            }
        }
        float cv = sigm(af) * cc + sigm(ai) * tanhf(ag);
        float hn = sigm(ao) * tanhf(cv);
        cc = cv;
        g_shs[(((rb ^ 1) * 2 + dir) * 32 + s) * 256 + j] = hn;
        if (MODE == 0) {
            int r = s * 16 + t, kp = dir * 256 + j;
            h16_store_one(g_stageS2 + ((size_t)((r >> 7) * 8 + (kp >> 6))) * TILE_BYTES,
                          r & 127, kp & 63, hn);
        } else {
            out[((size_t)s * 16 + t) * 512 + dir * 256 + j] = hn;
            float v1 = __shfl_down_sync(0xffffffffu, hn, 1);
            if (!(jl & 1)) {
                int kp = 32 + dir * 256 + j;
                int rbrow = (s * 16 + t) * 16;
                int blk = rbrow >> 7;
#pragma unroll
                for (int tw = 0; tw < 16; ++tw) {
                    float m = wm[sq * 256 + t * 16 + tw];
                    h16_store_pair(g_stageA, NCH_W0, blk, (rbrow & 127) + tw, kp, hn * m, v1 * m);
                }
            }
        }
        __threadfence();
        __syncthreads();
        tree_barrier(g_barT3, bid, tid, (unsigned)(base + tt + 1), 8u);
    }
}

// ---- attention ----
__global__ void attention_kernel(const float* __restrict__ q, const float* __restrict__ sent_enc,
                                 const int* __restrict__ words, float* __restrict__ map_out) {
    int bi = blockIdx.x, b = bi >> 4, i = bi & 15;
    __shared__ float se[16 * 513];
    __shared__ float sc[16][16];
    __shared__ float mp[16][16];
    __shared__ int kv[16];
    for (int x = threadIdx.x; x < 16 * 512; x += 256) {
        int jj = x >> 9, d = x & 511;
        se[jj * 513 + d] = sent_enc[((size_t)b * 16 + jj) * 512 + d];
    }
    if (threadIdx.x < 16) {
        int jj = threadIdx.x, any = 0;
        for (int tw = 0; tw < 16; ++tw) any |= (words[(b * 16 + jj) * 16 + tw] != 0);
        kv[jj] = any;
    }
    __syncthreads();
    {
        int cdx = threadIdx.x >> 4, jj = threadIdx.x & 15;
        const float* qr = q + ((size_t)bi * 16 + cdx) * 512;
        const float* ser = se + jj * 513;
        float s = 0.f;
#pragma unroll 4
        for (int d = 0; d < 512; ++d) s += qr[d] * ser[d];
        sc[cdx][jj] = s;
    }
    __syncthreads();
    if (threadIdx.x < 16) {
        int cdx = threadIdx.x;
        float v[16], m = -1e30f;
#pragma unroll
        for (int jj = 0; jj < 16; ++jj) {
            bool valid = (kv[jj] != 0) && (jj != i);
            v[jj] = valid ? sc[cdx][jj] : -1e9f;
            m = fmaxf(m, v[jj]);
        }
        float sum = 0.f;
#pragma unroll
        for (int jj = 0; jj < 16; ++jj) { v[jj] = expf(v[jj] - m); sum += v[jj]; }
        float inv = 1.f / sum;
#pragma unroll
        for (int jj = 0; jj < 16; ++jj) mp[cdx][jj] = v[jj] * inv;
    }
    __syncthreads();
    if (map_out != nullptr && threadIdx.x < 256) {
        int x = threadIdx.x;
        map_out[(size_t)bi * 256 + x] = mp[x >> 4][x & 15];
    }
    for (int x = threadIdx.x; x < 16 * 512; x += 256) {
        int cdx = x >> 9, d = x & 511;
        float s = 0.f;
#pragma unroll
        for (int jj = 0; jj < 16; ++jj) s += mp[cdx][jj] * se[jj * 513 + d];
        int r = bi * 16 + cdx;
        h16_store_one(g_stageD + ((size_t)(r >> 7) * 25 + (d >> 6)) * TILE_BYTES,
                      r & 127, d & 63, s);
    }
}

// ---- classifier: warp per row ----
__global__ void __launch_bounds__(256) classifier_kernel(
    const float* __restrict__ dec_out, const float* __restrict__ Wt,
    const float* __restrict__ bias, float* __restrict__ out) {
    __shared__ float res[8][16];
    int w = threadIdx.x >> 5, lane = threadIdx.x & 31;
    int m = blockIdx.x * 8 + w;
    const float4* x4 = (const float4*)(dec_out + (size_t)m * 1024);
    float4 xv[8];
#pragma unroll
    for (int i = 0; i < 8; ++i) xv[i] = x4[lane + i * 32];
#pragma unroll
    for (int n = 0; n < 15; ++n) {
        const float4* w4 = (const float4*)(Wt + n * 1024);
        float s = 0.f;
#pragma unroll
        for (int i = 0; i < 8; ++i) {
            float4 b = w4[lane + i * 32];
            s += xv[i].x * b.x + xv[i].y * b.y + xv[i].z * b.z + xv[i].w * b.w;
        }
#pragma unroll
        for (int o = 16; o; o >>= 1) s += __shfl_xor_sync(0xffffffffu, s, o);
        if (lane == 0) res[w][n] = s + bias[n];
    }
    __syncthreads();
    for (int i = threadIdx.x; i < 120; i += 256) {
        int mr = i / 15, n = i % 15;
        out[(size_t)(blockIdx.x * 8 + mr) * 15 + n] = res[mr][n];
    }
}

// ---- host ----
static void* symp(const void* s) { void* p = nullptr; cudaGetSymbolAddress(&p, s); return p; }

extern "C" void kernel_launch(void* const* d_in, const int* in_sizes, int n_in,
                              void* d_out, int out_size) {
    (void)in_sizes; (void)n_in;
    const int* sents = (const int*)d_in[0];
    const int* words = (const int*)d_in[1];
    const int* labels = (const int*)d_in[2];
    const float* word_embs = (const float*)d_in[3];
    const float* char_table = (const float*)d_in[4];
    const float* sWx0 = (const float*)d_in[5];
    const float* sWh0 = (const float*)d_in[6];
    const float* sb0 = (const float*)d_in[7];
    const float* sWx1 = (const float*)d_in[8];
    const float* sWh1 = (const float*)d_in[9];
    const float* sb1 = (const float*)d_in[10];
    const float* wWx0 = (const float*)d_in[11];
    const float* wWh0 = (const float*)d_in[12];
    const float* wb0 = (const float*)d_in[13];
    const float* wWx1 = (const float*)d_in[14];
    const float* wWh1 = (const float*)d_in[15];
    const float* wb1 = (const float*)d_in[16];
    const float* Wq = (const float*)d_in[17];
    const float* dWx = (const float*)d_in[18];
    const float* dWh = (const float*)d_in[19];
    const float* db = (const float*)d_in[20];
    const float* clsW = (const float*)d_in[21];
    const float* clsb = (const float*)d_in[22];
    float* out = (float*)d_out;

    float* pre_s = (float*)symp(g_pre_s);
    float* sent_enc = (float*)symp(g_sent_enc);
    float* pre_w = (float*)symp(g_pre_w);
    float* qbuf = (float*)symp(g_q);
    float* pre_d = (float*)symp(g_pre_d);
    float* dec_out = (float*)symp(g_dec_out);
    float* sWh0P = (float*)symp(g_sWh0P);
    float* sWh1P = (float*)symp(g_sWh1P);
    float* clsWT = (float*)symp(g_clsWT);
    const unsigned char* stA = (const unsigned char*)symp(g_stageA);
    const unsigned char* stD = (const unsigned char*)symp(g_stageD);
    const unsigned char* stS = (const unsigned char*)symp(g_stageS);
    const unsigned char* stS2 = (const unsigned char*)symp(g_stageS2);
    const unsigned char* stBs0 = (const unsigned char*)symp(g_stB_s0);
    const unsigned char* stBs1 = (const unsigned char*)symp(g_stB_s1);
    const unsigned char* stBw0 = (const unsigned char*)symp(g_stB_w0);
    const unsigned char* stBw1 = (const unsigned char*)symp(g_stB_w1);
    const unsigned char* stBq = (const unsigned char*)symp(g_stB_q);
    const unsigned char* stBdec = (const unsigned char*)symp(g_stB_dec);
    const unsigned char* stWw = (const unsigned char*)symp(g_stWw);

    cudaFuncSetAttribute(tgemm_kernel, cudaFuncAttributeMaxDynamicSharedMemorySize, TG_SMEM);
    cudaFuncSetAttribute(dec_persist_kernel, cudaFuncAttributeMaxDynamicSharedMemorySize, DEC_SMEM);
    cudaFuncSetAttribute(wordrec_kernel, cudaFuncAttributeMaxDynamicSharedMemorySize, WR_SMEM);
    cudaFuncSetAttribute(sentrec_kernel<0>, cudaFuncAttributeMaxDynamicSharedMemorySize, SR_SMEM);
    cudaFuncSetAttribute(sentrec_kernel<1>, cudaFuncAttributeMaxDynamicSharedMemorySize, SR_SMEM);

    const size_t wwLayer = 2ul * 16 * 8 * TILE_BYTES;

    prep_kernel<<<PREP_BLOCKS, 256>>>(sWh0, sWh1, wWh0, wWh1, dWh, wWx0, wWx1, Wq, dWx,
                                      words, char_table, sents, word_embs, labels, clsW,
                                      sWx0, sWx1);
    tgemm_kernel<<<dim3(16, 4), 512, TG_SMEM>>>(stS, stBs0, sb0, pre_s, 2048, 5);
    sentrec_kernel<0><<<64, 256, SR_SMEM>>>(pre_s, sWh0P, nullptr, nullptr, 0);
    tgemm_kernel<<<dim3(16, 4), 512, TG_SMEM>>>(stS2, stBs1, sb1, pre_s, 2048, 8);
    sentrec_kernel<1><<<64, 256, SR_SMEM>>>(pre_s, sWh1P, sent_enc, words, 16);
    tgemm_kernel<<<dim3(32, 64), 512, TG_SMEM>>>(stA, stBw0, wb0, pre_w, 4096, NCH_W0);
    wordrec_kernel<<<128, 256, WR_SMEM>>>(stWw, pre_w, 0, 0);
    tgemm_kernel<<<dim3(32, 64), 512, TG_SMEM>>>(stA, stBw1, wb1, pre_w, 4096, NCH_W1);
    wordrec_kernel<<<128, 256, WR_SMEM>>>(stWw + wwLayer, pre_w, 1, 16);
    tgemm_kernel<<<dim3(4, 64), 512, TG_SMEM>>>(stA, stBq, nullptr, qbuf, 512, NCH_Q);
    float* map_out = (out_size >= (NR_ * 15 + 131072)) ? (out + NR_ * 15) : nullptr;
    attention_kernel<<<NSEQ_, 256>>>(qbuf, sent_enc, words, map_out);
    tgemm_kernel<<<dim3(32, 64), 512, TG_SMEM>>>(stD, stBdec, db, pre_d, 4096, NCH_DEC);
    dec_persist_kernel<<<128, 256, DEC_SMEM>>>(pre_d, dec_out);
    classifier_kernel<<<NR_ / 8, 256>>>(dec_out, clsWT, clsb, out);
}